// round 1
// baseline (speedup 1.0000x reference)
#include <cuda_runtime.h>
#include <math.h>

#define T_STEPS 144000
#define NB 10        // output bands
#define NOUT (2*T_STEPS*NB)

// ---------------- device scratch (no allocs allowed) ----------------
// Transposed, float4-packed weights: Wt[k4*512 + g] = {W[g][4k4..4k4+3]}
__device__ float4 g_whh0_t[32*512];
__device__ float4 g_wih1_t[32*512];
__device__ float4 g_whh1_t[32*512];
__device__ float  g_xp0[1024];   // xproj0[b*512+g] = latent@w_ih0^T + b_ih0 + b_hh0
__device__ float  g_b1v[512];    // b_ih1 + b_hh1
__device__ int    g_fix[2];      // {t_detect, period}

// ---------------- prep: transpose the three recurrent/input matrices ----------------
__global__ void k_transpose(const float* __restrict__ whh0,
                            const float* __restrict__ wih1,
                            const float* __restrict__ whh1) {
    int idx = blockIdx.x * blockDim.x + threadIdx.x;     // 0 .. 3*16384-1
    if (idx >= 3 * 16384) return;
    int m  = idx >> 14;
    int r  = idx & 16383;
    int k4 = r >> 9;
    int g  = r & 511;
    const float* src = (m == 0 ? whh0 : (m == 1 ? wih1 : whh1)) + g * 128 + k4 * 4;
    float4 v = *reinterpret_cast<const float4*>(src);
    float4* dst = (m == 0 ? g_whh0_t : (m == 1 ? g_wih1_t : g_whh1_t));
    dst[(k4 << 9) + g] = v;
}

// ---------------- prep: encoder MLP + constant input projection ----------------
__global__ void k_prep(const float* __restrict__ x,
                       const float* __restrict__ w1,  const float* __restrict__ eb1,
                       const float* __restrict__ w2,  const float* __restrict__ eb2,
                       const float* __restrict__ wih0,
                       const float* __restrict__ bih0, const float* __restrict__ bhh0,
                       const float* __restrict__ bih1, const float* __restrict__ bhh1) {
    __shared__ float l1[2][64];
    __shared__ float l2[2][128];
    int tid = threadIdx.x;   // 512 threads

    if (tid < 128) {
        int b = tid >> 6, j = tid & 63;
        float a = eb1[j];
        #pragma unroll
        for (int k = 0; k < 16; k++) a += x[b * 16 + k] * w1[j * 16 + k];
        l1[b][j] = fmaxf(a, 0.f);
    }
    __syncthreads();
    if (tid < 256) {
        int b = tid >> 7, j = tid & 127;
        float a = eb2[j];
        #pragma unroll 8
        for (int k = 0; k < 64; k++) a += l1[b][k] * w2[j * 64 + k];
        l2[b][j] = fmaxf(a, 0.f);
    }
    __syncthreads();
    int g = tid;
    float base = bih0[g] + bhh0[g];
    #pragma unroll
    for (int b = 0; b < 2; b++) {
        float a = base;
        #pragma unroll 8
        for (int k = 0; k < 128; k++) a += l2[b][k] * wih0[g * 128 + k];
        g_xp0[b * 512 + g] = a;
    }
    g_b1v[g] = bih1[g] + bhh1[g];
}

// ---------------- sequential recurrence with bitwise period detection ----------------
__device__ __forceinline__ float sigm(float v) { return 1.0f / (1.0f + expf(-v)); }

__global__ void __launch_bounds__(512, 1)
k_seq(const float* __restrict__ wout, const float* __restrict__ bout,
      float* __restrict__ out) {
    __shared__ __align__(16) float s_state[1024];   // h0[2][128] | c0 | h1 | c1
    __shared__ int   s_prev[4][1024];               // ring of last 4 states (as bits)
    __shared__ float s_g0[1024];                    // gates layer0 [b*512+g]
    __shared__ float s_g1[1024];                    // gates layer1
    __shared__ float s_xp0[1024];
    __shared__ float s_b1[512];
    __shared__ float s_wout[1280];                  // [10][128]
    __shared__ float s_bout[16];

    const int tid = threadIdx.x;

    s_state[tid] = 0.f; s_state[tid + 512] = 0.f;
    #pragma unroll
    for (int p = 0; p < 4; p++) { s_prev[p][tid] = 0x7f800001; s_prev[p][tid + 512] = 0x7f800001; }
    s_xp0[tid] = g_xp0[tid]; s_xp0[tid + 512] = g_xp0[tid + 512];
    s_b1[tid & 511] = g_b1v[tid & 511];
    for (int i = tid; i < 1280; i += 512) s_wout[i] = wout[i];
    if (tid < NB) s_bout[tid] = bout[tid];
    __syncthreads();

    float* h0 = s_state;       float* c0 = s_state + 256;
    float* h1 = s_state + 512; float* c1 = s_state + 768;

    int td = T_STEPS, per = 1;

    for (int t = 0; t < T_STEPS; t++) {
        // ---- layer 0 gates: thread g handles gate row g for both batches ----
        {
            float a0 = s_xp0[tid], a1 = s_xp0[512 + tid];
            #pragma unroll 8
            for (int k4 = 0; k4 < 32; k4++) {
                float4 w  = g_whh0_t[(k4 << 9) + tid];
                float4 xa = *reinterpret_cast<const float4*>(h0 + (k4 << 2));
                float4 xb = *reinterpret_cast<const float4*>(h0 + 128 + (k4 << 2));
                a0 += w.x * xa.x + w.y * xa.y + w.z * xa.z + w.w * xa.w;
                a1 += w.x * xb.x + w.y * xb.y + w.z * xb.z + w.w * xb.w;
            }
            s_g0[tid] = a0; s_g0[512 + tid] = a1;
        }
        __syncthreads();
        // ---- layer 0 cell ----
        if (tid < 256) {
            int b = tid >> 7, j = tid & 127, o = (b << 9), s = (b << 7) + j;
            float ii = sigm(s_g0[o + j]);
            float ff = sigm(s_g0[o + 128 + j]);
            float gg = tanhf(s_g0[o + 256 + j]);
            float oo = sigm(s_g0[o + 384 + j]);
            float c = ff * c0[s] + ii * gg;
            c0[s] = c; h0[s] = oo * tanhf(c);
        }
        __syncthreads();
        // ---- layer 1 gates ----
        {
            float a0 = s_b1[tid], a1 = s_b1[tid];
            #pragma unroll 4
            for (int k4 = 0; k4 < 32; k4++) {
                float4 wi = g_wih1_t[(k4 << 9) + tid];
                float4 wh = g_whh1_t[(k4 << 9) + tid];
                float4 xa = *reinterpret_cast<const float4*>(h0 + (k4 << 2));
                float4 xb = *reinterpret_cast<const float4*>(h0 + 128 + (k4 << 2));
                float4 ya = *reinterpret_cast<const float4*>(h1 + (k4 << 2));
                float4 yb = *reinterpret_cast<const float4*>(h1 + 128 + (k4 << 2));
                a0 += wi.x * xa.x + wi.y * xa.y + wi.z * xa.z + wi.w * xa.w;
                a0 += wh.x * ya.x + wh.y * ya.y + wh.z * ya.z + wh.w * ya.w;
                a1 += wi.x * xb.x + wi.y * xb.y + wi.z * xb.z + wi.w * xb.w;
                a1 += wh.x * yb.x + wh.y * yb.y + wh.z * yb.z + wh.w * yb.w;
            }
            s_g1[tid] = a0; s_g1[512 + tid] = a1;
        }
        __syncthreads();
        // ---- layer 1 cell ----
        if (tid < 256) {
            int b = tid >> 7, j = tid & 127, o = (b << 9), s = (b << 7) + j;
            float ii = sigm(s_g1[o + j]);
            float ff = sigm(s_g1[o + 128 + j]);
            float gg = tanhf(s_g1[o + 256 + j]);
            float oo = sigm(s_g1[o + 384 + j]);
            float c = ff * c1[s] + ii * gg;
            c1[s] = c; h1[s] = oo * tanhf(c);
        }
        __syncthreads();
        // ---- output head for this step ----
        if (tid < 2 * NB) {
            int b = tid / NB, k = tid - NB * b;
            float a = s_bout[k];
            #pragma unroll 8
            for (int j = 0; j < 128; j++) a += s_wout[(k << 7) + j] * h1[(b << 7) + j];
            out[(size_t)b * T_STEPS * NB + (size_t)t * NB + k] = a;
        }
        // ---- bitwise periodicity check (periods 1..4) ----
        int i0 = __float_as_int(s_state[tid]);
        int i1 = __float_as_int(s_state[512 + tid]);
        int e1 = (i0 == s_prev[(t - 1) & 3][tid]) && (i1 == s_prev[(t - 1) & 3][tid + 512]);
        int e2 = (i0 == s_prev[(t - 2) & 3][tid]) && (i1 == s_prev[(t - 2) & 3][tid + 512]);
        int e3 = (i0 == s_prev[(t - 3) & 3][tid]) && (i1 == s_prev[(t - 3) & 3][tid + 512]);
        int e4 = (i0 == s_prev[t & 3][tid])       && (i1 == s_prev[t & 3][tid + 512]);
        int a1r = __syncthreads_and(e1);
        int a2r = __syncthreads_and(e2);
        int a3r = __syncthreads_and(e3);
        int a4r = __syncthreads_and(e4);
        s_prev[t & 3][tid] = i0; s_prev[t & 3][tid + 512] = i1;
        if (a1r | a2r | a3r | a4r) {
            per = a1r ? 1 : (a2r ? 2 : (a3r ? 3 : 4));
            td  = t + 1;
            break;
        }
    }

    if (tid == 0) { g_fix[0] = td; g_fix[1] = per; }
}

// ---------------- parallel periodic tail fill ----------------
__global__ void k_fill(float* __restrict__ out) {
    int td = g_fix[0], p = g_fix[1];
    int idx = blockIdx.x * blockDim.x + threadIdx.x;
    if (idx >= NOUT) return;
    int k = idx % NB;
    int r = idx / NB;
    int t = r % T_STEPS;
    int b = r / T_STEPS;
    if (t < td) return;                      // written exactly by k_seq
    int src = td - p + ((t - td) % p);       // src in [td-p, td) -> written by k_seq
    out[idx] = out[(size_t)b * T_STEPS * NB + (size_t)src * NB + k];
}

// ---------------- launch ----------------
extern "C" void kernel_launch(void* const* d_in, const int* in_sizes, int n_in,
                              void* d_out, int out_size) {
    const float* x     = (const float*)d_in[0];
    const float* w1    = (const float*)d_in[1];
    const float* b1    = (const float*)d_in[2];
    const float* w2    = (const float*)d_in[3];
    const float* b2    = (const float*)d_in[4];
    const float* w_ih0 = (const float*)d_in[5];
    const float* w_hh0 = (const float*)d_in[6];
    const float* b_ih0 = (const float*)d_in[7];
    const float* b_hh0 = (const float*)d_in[8];
    const float* w_ih1 = (const float*)d_in[9];
    const float* w_hh1 = (const float*)d_in[10];
    const float* b_ih1 = (const float*)d_in[11];
    const float* b_hh1 = (const float*)d_in[12];
    const float* w_out = (const float*)d_in[13];
    const float* b_out = (const float*)d_in[14];
    float* out = (float*)d_out;

    k_transpose<<<192, 256>>>(w_hh0, w_ih1, w_hh1);
    k_prep<<<1, 512>>>(x, w1, b1, w2, b2, w_ih0, b_ih0, b_hh0, b_ih1, b_hh1);
    k_seq<<<1, 512>>>(w_out, b_out, out);
    k_fill<<<(NOUT + 255) / 256, 256>>>(out);
}

// round 2
// speedup vs baseline: 4284.1848x; 4284.1848x over previous
#include <cuda_runtime.h>
#include <math.h>

#define T_STEPS 144000
#define NB 10        // output bands
#define NOUT (2*T_STEPS*NB)
#define EPS_DET 4e-6f

// ---------------- device scratch (no allocs allowed) ----------------
// Transposed, float4-packed weights: Wt[k4*512 + g] = {W[g][4k4..4k4+3]}
__device__ float4 g_whh0_t[32*512];
__device__ float4 g_wih1_t[32*512];
__device__ float4 g_whh1_t[32*512];
__device__ float  g_xp0[1024];   // xproj0[b*512+g] = latent@w_ih0^T + b_ih0 + b_hh0
__device__ float  g_b1v[512];    // b_ih1 + b_hh1
__device__ int    g_fix[2];      // {t_detect, period}

// ---------------- prep: transpose the three recurrent/input matrices ----------------
__global__ void k_transpose(const float* __restrict__ whh0,
                            const float* __restrict__ wih1,
                            const float* __restrict__ whh1) {
    int idx = blockIdx.x * blockDim.x + threadIdx.x;     // 0 .. 3*16384-1
    if (idx >= 3 * 16384) return;
    int m  = idx >> 14;
    int r  = idx & 16383;
    int k4 = r >> 9;
    int g  = r & 511;
    const float* src = (m == 0 ? whh0 : (m == 1 ? wih1 : whh1)) + g * 128 + k4 * 4;
    float4 v = *reinterpret_cast<const float4*>(src);
    float4* dst = (m == 0 ? g_whh0_t : (m == 1 ? g_wih1_t : g_whh1_t));
    dst[(k4 << 9) + g] = v;
}

// ---------------- prep: encoder MLP + constant input projection ----------------
__global__ void k_prep(const float* __restrict__ x,
                       const float* __restrict__ w1,  const float* __restrict__ eb1,
                       const float* __restrict__ w2,  const float* __restrict__ eb2,
                       const float* __restrict__ wih0,
                       const float* __restrict__ bih0, const float* __restrict__ bhh0,
                       const float* __restrict__ bih1, const float* __restrict__ bhh1) {
    __shared__ float l1[2][64];
    __shared__ float l2[2][128];
    int tid = threadIdx.x;   // 512 threads

    if (tid < 128) {
        int b = tid >> 6, j = tid & 63;
        float a = eb1[j];
        #pragma unroll
        for (int k = 0; k < 16; k++) a += x[b * 16 + k] * w1[j * 16 + k];
        l1[b][j] = fmaxf(a, 0.f);
    }
    __syncthreads();
    if (tid < 256) {
        int b = tid >> 7, j = tid & 127;
        float a = eb2[j];
        #pragma unroll 8
        for (int k = 0; k < 64; k++) a += l1[b][k] * w2[j * 64 + k];
        l2[b][j] = fmaxf(a, 0.f);
    }
    __syncthreads();
    int g = tid;
    float base = bih0[g] + bhh0[g];
    #pragma unroll
    for (int b = 0; b < 2; b++) {
        float a = base;
        #pragma unroll 8
        for (int k = 0; k < 128; k++) a += l2[b][k] * wih0[g * 128 + k];
        g_xp0[b * 512 + g] = a;
    }
    g_b1v[g] = bih1[g] + bhh1[g];
}

// ---------------- sequential recurrence with epsilon period detection ----------------
__device__ __forceinline__ float sigm(float v) { return 1.0f / (1.0f + expf(-v)); }

__global__ void __launch_bounds__(512, 1)
k_seq(const float* __restrict__ wout, const float* __restrict__ bout,
      float* __restrict__ out) {
    __shared__ __align__(16) float s_state[1024];   // h0[2][128] | c0 | h1 | c1
    __shared__ float s_ring[4][1024];               // ring of last 4 states
    __shared__ float s_g0[1024];                    // gates layer0 [b*512+g]
    __shared__ float s_g1[1024];                    // gates layer1
    __shared__ float s_xp0[1024];
    __shared__ float s_b1[512];
    __shared__ float s_wout[1280];                  // [10][128]
    __shared__ float s_bout[16];
    __shared__ int   s_mask[2];                     // double-buffered match mask

    const int tid = threadIdx.x;

    s_state[tid] = 0.f; s_state[tid + 512] = 0.f;
    #pragma unroll
    for (int p = 0; p < 4; p++) { s_ring[p][tid] = 1e30f; s_ring[p][tid + 512] = 1e30f; }
    s_xp0[tid] = g_xp0[tid]; s_xp0[tid + 512] = g_xp0[tid + 512];
    s_b1[tid & 511] = g_b1v[tid & 511];
    for (int i = tid; i < 1280; i += 512) s_wout[i] = wout[i];
    if (tid < NB) s_bout[tid] = bout[tid];
    if (tid < 2) s_mask[tid] = 0;                   // no match pending
    __syncthreads();

    float* h0 = s_state;       float* c0 = s_state + 256;
    float* h1 = s_state + 512; float* c1 = s_state + 768;

    int td = T_STEPS, per = 1;

    for (int t = 0; t < T_STEPS; t++) {
        // ---- layer 0 gates: thread g handles gate row g for both batches ----
        {
            float a0 = s_xp0[tid], a1 = s_xp0[512 + tid];
            #pragma unroll 8
            for (int k4 = 0; k4 < 32; k4++) {
                float4 w  = g_whh0_t[(k4 << 9) + tid];
                float4 xa = *reinterpret_cast<const float4*>(h0 + (k4 << 2));
                float4 xb = *reinterpret_cast<const float4*>(h0 + 128 + (k4 << 2));
                a0 += w.x * xa.x + w.y * xa.y + w.z * xa.z + w.w * xa.w;
                a1 += w.x * xb.x + w.y * xb.y + w.z * xb.z + w.w * xb.w;
            }
            s_g0[tid] = a0; s_g0[512 + tid] = a1;
        }
        __syncthreads();

        // ---- check last step's accumulated match mask (visible via the sync above) ----
        int mdet = s_mask[(t + 1) & 1];     // slot written at step t-1
        if (t >= 10 && mdet) {
            per = (mdet & 1) ? 1 : ((mdet & 2) ? 2 : ((mdet & 4) ? 3 : 4));
            td  = t;                         // outputs written for steps < t
            break;
        }
        if (tid == 0) s_mask[t & 1] = 0xF;   // arm accumulator for this step

        // ---- layer 0 cell ----
        if (tid < 256) {
            int b = tid >> 7, j = tid & 127, o = (b << 9), s = (b << 7) + j;
            float ii = sigm(s_g0[o + j]);
            float ff = sigm(s_g0[o + 128 + j]);
            float gg = tanhf(s_g0[o + 256 + j]);
            float oo = sigm(s_g0[o + 384 + j]);
            float c = ff * c0[s] + ii * gg;
            c0[s] = c; h0[s] = oo * tanhf(c);
        }
        __syncthreads();
        // ---- layer 1 gates ----
        {
            float a0 = s_b1[tid], a1 = s_b1[tid];
            #pragma unroll 4
            for (int k4 = 0; k4 < 32; k4++) {
                float4 wi = g_wih1_t[(k4 << 9) + tid];
                float4 wh = g_whh1_t[(k4 << 9) + tid];
                float4 xa = *reinterpret_cast<const float4*>(h0 + (k4 << 2));
                float4 xb = *reinterpret_cast<const float4*>(h0 + 128 + (k4 << 2));
                float4 ya = *reinterpret_cast<const float4*>(h1 + (k4 << 2));
                float4 yb = *reinterpret_cast<const float4*>(h1 + 128 + (k4 << 2));
                a0 += wi.x * xa.x + wi.y * xa.y + wi.z * xa.z + wi.w * xa.w;
                a0 += wh.x * ya.x + wh.y * ya.y + wh.z * ya.z + wh.w * ya.w;
                a1 += wi.x * xb.x + wi.y * xb.y + wi.z * xb.z + wi.w * xb.w;
                a1 += wh.x * yb.x + wh.y * yb.y + wh.z * yb.z + wh.w * yb.w;
            }
            s_g1[tid] = a0; s_g1[512 + tid] = a1;
        }
        __syncthreads();
        // ---- layer 1 cell ----
        if (tid < 256) {
            int b = tid >> 7, j = tid & 127, o = (b << 9), s = (b << 7) + j;
            float ii = sigm(s_g1[o + j]);
            float ff = sigm(s_g1[o + 128 + j]);
            float gg = tanhf(s_g1[o + 256 + j]);
            float oo = sigm(s_g1[o + 384 + j]);
            float c = ff * c1[s] + ii * gg;
            c1[s] = c; h1[s] = oo * tanhf(c);
        }
        __syncthreads();
        // ---- output head for this step ----
        if (tid < 2 * NB) {
            int b = tid / NB, k = tid - NB * b;
            float a = s_bout[k];
            #pragma unroll 8
            for (int j = 0; j < 128; j++) a += s_wout[(k << 7) + j] * h1[(b << 7) + j];
            out[(size_t)b * T_STEPS * NB + (size_t)t * NB + k] = a;
        }
        // ---- epsilon periodicity flags (periods 1..4), read next step ----
        {
            float v0 = s_state[tid], v1 = s_state[512 + tid];
            int m = 0;
            #pragma unroll
            for (int p = 1; p <= 4; p++) {
                int sl = (t - p) & 3;
                int e = (fabsf(v0 - s_ring[sl][tid])       <= EPS_DET) &&
                        (fabsf(v1 - s_ring[sl][tid + 512]) <= EPS_DET);
                m |= e << (p - 1);
            }
            s_ring[t & 3][tid] = v0; s_ring[t & 3][tid + 512] = v1;
            m = __reduce_and_sync(0xFFFFFFFFu, m);
            if ((tid & 31) == 0 && m != 0xF) atomicAnd(&s_mask[t & 1], m);
        }
    }

    if (tid == 0) { g_fix[0] = td; g_fix[1] = per; }
}

// ---------------- parallel periodic tail fill ----------------
__global__ void k_fill(float* __restrict__ out) {
    int td = g_fix[0], p = g_fix[1];
    int idx = blockIdx.x * blockDim.x + threadIdx.x;
    if (idx >= NOUT) return;
    int k = idx % NB;
    int r = idx / NB;
    int t = r % T_STEPS;
    int b = r / T_STEPS;
    if (t < td) return;                      // written exactly by k_seq
    int src = td - p + ((t - td) % p);       // src in [td-p, td) -> written by k_seq
    out[idx] = out[(size_t)b * T_STEPS * NB + (size_t)src * NB + k];
}

// ---------------- launch ----------------
extern "C" void kernel_launch(void* const* d_in, const int* in_sizes, int n_in,
                              void* d_out, int out_size) {
    const float* x     = (const float*)d_in[0];
    const float* w1    = (const float*)d_in[1];
    const float* b1    = (const float*)d_in[2];
    const float* w2    = (const float*)d_in[3];
    const float* b2    = (const float*)d_in[4];
    const float* w_ih0 = (const float*)d_in[5];
    const float* w_hh0 = (const float*)d_in[6];
    const float* b_ih0 = (const float*)d_in[7];
    const float* b_hh0 = (const float*)d_in[8];
    const float* w_ih1 = (const float*)d_in[9];
    const float* w_hh1 = (const float*)d_in[10];
    const float* b_ih1 = (const float*)d_in[11];
    const float* b_hh1 = (const float*)d_in[12];
    const float* w_out = (const float*)d_in[13];
    const float* b_out = (const float*)d_in[14];
    float* out = (float*)d_out;

    k_transpose<<<192, 256>>>(w_hh0, w_ih1, w_hh1);
    k_prep<<<1, 512>>>(x, w1, b1, w2, b2, w_ih0, b_ih0, b_hh0, b_ih1, b_hh1);
    k_seq<<<1, 512>>>(w_out, b_out, out);
    k_fill<<<(NOUT + 255) / 256, 256>>>(out);
}

// round 5
// speedup vs baseline: 7204.7939x; 1.6817x over previous
#include <cuda_runtime.h>
#include <math.h>
#include <stdint.h>

#define T_STEPS 144000
#define NB 10
#define NOUT (2*T_STEPS*NB)
#define EPS_DET 4e-6f
#define CLUSTER_N 4
#define THREADS 256

// ---------------- device scratch ----------------
__device__ float4 g_whh0_t[32*512];   // [k4][g]
__device__ float4 g_wih1_t[32*512];
__device__ float4 g_whh1_t[32*512];
__device__ float4 g_wih0_t[32*512];
__device__ int    g_fix[2];           // {t_detect, period}

// ---------------- PTX helpers ----------------
__device__ __forceinline__ uint32_t smem_u32(const void* p) {
    uint32_t a;
    asm("{ .reg .u64 t; cvta.to.shared.u64 t, %1; cvt.u32.u64 %0, t; }" : "=r"(a) : "l"(p));
    return a;
}
__device__ __forceinline__ uint32_t mapa_rank(uint32_t local, uint32_t rank) {
    uint32_t r;
    asm("mapa.shared::cluster.u32 %0, %1, %2;" : "=r"(r) : "r"(local), "r"(rank));
    return r;
}
__device__ __forceinline__ void st_cluster_f32(uint32_t addr, float v) {
    asm volatile("st.shared::cluster.f32 [%0], %1;" :: "r"(addr), "f"(v) : "memory");
}
__device__ __forceinline__ void st_cluster_u32(uint32_t addr, uint32_t v) {
    asm volatile("st.shared::cluster.u32 [%0], %1;" :: "r"(addr), "r"(v) : "memory");
}
__device__ __forceinline__ void mbar_init(uint32_t addr, uint32_t cnt) {
    asm volatile("mbarrier.init.shared.b64 [%0], %1;" :: "r"(addr), "r"(cnt) : "memory");
}
__device__ __forceinline__ void mbar_arrive_cluster(uint32_t addr) {
    asm volatile("mbarrier.arrive.release.cluster.shared::cluster.b64 _, [%0];"
                 :: "r"(addr) : "memory");
}
__device__ __forceinline__ void mbar_wait_parity(uint32_t addr, uint32_t parity) {
    asm volatile(
        "{\n\t.reg .pred P;\n\t"
        "WLP_%=:\n\t"
        "mbarrier.try_wait.parity.acquire.cluster.shared::cta.b64 P, [%0], %1, 0x989680;\n\t"
        "@P bra.uni WDN_%=;\n\t"
        "bra.uni WLP_%=;\n\t"
        "WDN_%=:\n\t}"
        :: "r"(addr), "r"(parity) : "memory");
}
__device__ __forceinline__ void cluster_sync_all() {
    asm volatile("barrier.cluster.arrive.aligned;" ::: "memory");
    asm volatile("barrier.cluster.wait.aligned;" ::: "memory");
}
__device__ __forceinline__ uint32_t ctarank() {
    uint32_t r; asm("mov.u32 %0, %%cluster_ctarank;" : "=r"(r)); return r;
}
// fast gates: MUFU-based, rel err ~1e-6
__device__ __forceinline__ float ex2a(float x) { float r; asm("ex2.approx.f32 %0, %1;" : "=f"(r) : "f"(x)); return r; }
__device__ __forceinline__ float rcpa(float x) { float r; asm("rcp.approx.f32 %0, %1;" : "=f"(r) : "f"(x)); return r; }
__device__ __forceinline__ float sigm(float v)  { return rcpa(1.0f + ex2a(-1.4426950408889634f * v)); }
__device__ __forceinline__ float tanhx(float v) { return 1.0f - 2.0f * rcpa(1.0f + ex2a(2.8853900817779268f * v)); }

// ---------------- transpose 4 matrices into [k4][g] ----------------
__global__ void k_transpose(const float* __restrict__ whh0,
                            const float* __restrict__ wih1,
                            const float* __restrict__ whh1,
                            const float* __restrict__ wih0) {
    int idx = blockIdx.x * blockDim.x + threadIdx.x;     // 0 .. 4*16384-1
    if (idx >= 4 * 16384) return;
    int m  = idx >> 14;
    int r  = idx & 16383;
    int k4 = r >> 9;
    int g  = r & 511;
    const float* src = (m == 0 ? whh0 : (m == 1 ? wih1 : (m == 2 ? whh1 : wih0)));
    float4 v = *reinterpret_cast<const float4*>(src + g * 128 + k4 * 4);
    float4* dst = (m == 0 ? g_whh0_t : (m == 1 ? g_wih1_t : (m == 2 ? g_whh1_t : g_wih0_t)));
    dst[(k4 << 9) + g] = v;
}

// ---------------- clustered sequential kernel ----------------
__global__ void __launch_bounds__(THREADS, 1) __cluster_dims__(CLUSTER_N, 1, 1)
k_seq(const float* __restrict__ x,
      const float* __restrict__ w1e,  const float* __restrict__ eb1,
      const float* __restrict__ w2e,  const float* __restrict__ eb2,
      const float* __restrict__ bih0, const float* __restrict__ bhh0,
      const float* __restrict__ bih1, const float* __restrict__ bhh1,
      const float* __restrict__ wout, const float* __restrict__ bout,
      float* __restrict__ out) {
    __shared__ __align__(16) float s_h0[2][256];   // [slot][b*128 + unit]
    __shared__ __align__(16) float s_h1[2][256];
    __shared__ float s_g0p[2][256];                // [khalf][b*128 + r]
    __shared__ float s_g1p[2][256];
    __shared__ float s_xp0[256];                   // [b*128 + r]
    __shared__ float s_b1[128];
    __shared__ float s_wout[5*128];
    __shared__ float s_boutv[8];
    __shared__ float s_l1[128];
    __shared__ __align__(16) float s_l2[256];
    __shared__ int   s_lmask[2];
    __shared__ int   s_mslot[2][4];                // [slot][src rank]
    __shared__ __align__(8) unsigned long long s_barH0, s_barH1;

    const int tid = threadIdx.x;
    const uint32_t rank = ctarank();
    const int r = tid & 127;
    const int khalf = tid >> 7;
    const int grow = ((r >> 5) << 7) + (int)(rank << 5) + (r & 31);  // global gate row

    // ---- encoder MLP (redundant per CTA) ----
    if (tid < 128) { int b = tid >> 6, j = tid & 63;
        float a = eb1[j];
        #pragma unroll
        for (int k = 0; k < 16; k++) a += x[b * 16 + k] * w1e[j * 16 + k];
        s_l1[b * 64 + j] = fmaxf(a, 0.f);
    }
    __syncthreads();
    { int b = tid >> 7, j = tid & 127;
        float a = eb2[j];
        #pragma unroll 8
        for (int k = 0; k < 64; k++) a += s_l1[b * 64 + k] * w2e[j * 64 + k];
        s_l2[b * 128 + j] = fmaxf(a, 0.f);
    }
    __syncthreads();
    { int b = tid >> 7;
        float a = bih0[grow] + bhh0[grow];
        const float4* l2v = (const float4*)(s_l2 + b * 128);
        #pragma unroll 8
        for (int k4 = 0; k4 < 32; k4++) {
            float4 w = g_wih0_t[(k4 << 9) + grow];
            float4 l = l2v[k4];
            a += w.x * l.x + w.y * l.y + w.z * l.z + w.w * l.w;
        }
        s_xp0[b * 128 + r] = a;
    }
    if (tid < 128) s_b1[tid] = bih1[grow] + bhh1[grow];
    for (int idx = tid; idx < 5 * 128; idx += THREADS) {
        int i = idx >> 7, j = idx & 127;
        int band = ((int)rank * 5 + i) % NB;
        s_wout[idx] = wout[band * 128 + j];
    }
    if (tid < 5) s_boutv[tid] = bout[((int)rank * 5 + tid) % NB];
    { s_h0[0][tid] = 0.f; s_h0[1][tid] = 0.f; s_h1[0][tid] = 0.f; s_h1[1][tid] = 0.f; }
    if (tid < 2) s_lmask[tid] = 0xF;
    if (tid < 8) s_mslot[tid >> 2][tid & 3] = 0xF;
    if (tid == 0) {
        mbar_init(smem_u32(&s_barH0), 64 * CLUSTER_N);
        mbar_init(smem_u32(&s_barH1), 64 * CLUSTER_N + CLUSTER_N);
    }
    __syncthreads();
    cluster_sync_all();

    const uint32_t barH0_l = smem_u32(&s_barH0);
    const uint32_t barH1_l = smem_u32(&s_barH1);
    uint32_t rb0[4], rb1[4], rh0[2][4], rh1[2][4], rmk[2][4];
    float c0r = 0.f, c1r = 0.f;
    float hist[4][4];
    const int wb = tid >> 5, wu = tid & 31;
    if (tid < 64) {
        int off = wb * 128 + (int)(rank << 5) + wu;
        #pragma unroll
        for (int rr = 0; rr < 4; rr++) {
            rb0[rr] = mapa_rank(barH0_l, rr);
            rb1[rr] = mapa_rank(barH1_l, rr);
            rh0[0][rr] = mapa_rank(smem_u32(&s_h0[0][off]), rr);
            rh0[1][rr] = mapa_rank(smem_u32(&s_h0[1][off]), rr);
            rh1[0][rr] = mapa_rank(smem_u32(&s_h1[0][off]), rr);
            rh1[1][rr] = mapa_rank(smem_u32(&s_h1[1][off]), rr);
        }
        #pragma unroll
        for (int p = 0; p < 4; p++)
            #pragma unroll
            for (int i = 0; i < 4; i++) hist[p][i] = 1e30f;
    }
    if (tid == 0) {
        #pragma unroll
        for (int rr = 0; rr < 4; rr++) {
            rmk[0][rr] = mapa_rank(smem_u32(&s_mslot[0][rank]), rr);
            rmk[1][rr] = mapa_rank(smem_u32(&s_mslot[1][rank]), rr);
        }
    }

    int td = T_STEPS, per = 1;

    for (int t = 0; t <= T_STEPS; t++) {
        if (tid == 0) s_lmask[t & 1] = 0xF;

        // ===== layer 0 gates (uses h0(t-1); barH0(t-1) acquired last step) =====
        {
            const float* h = s_h0[(t + 1) & 1];
            float a0 = 0.f, a0b = 0.f, a1 = 0.f, a1b = 0.f;
            if (khalf == 0) { a0 = s_xp0[r]; a1 = s_xp0[128 + r]; }
            int k4lo = khalf << 4;
            #pragma unroll
            for (int k4 = 0; k4 < 16; k4 += 2) {
                float4 w  = g_whh0_t[((k4lo + k4) << 9) + grow];
                float4 w2 = g_whh0_t[((k4lo + k4 + 1) << 9) + grow];
                float4 ha  = *(const float4*)(h + ((k4lo + k4) << 2));
                float4 ha2 = *(const float4*)(h + ((k4lo + k4 + 1) << 2));
                float4 hb  = *(const float4*)(h + 128 + ((k4lo + k4) << 2));
                float4 hb2 = *(const float4*)(h + 128 + ((k4lo + k4 + 1) << 2));
                a0  += w.x * ha.x + w.y * ha.y + w.z * ha.z + w.w * ha.w;
                a0b += w2.x * ha2.x + w2.y * ha2.y + w2.z * ha2.z + w2.w * ha2.w;
                a1  += w.x * hb.x + w.y * hb.y + w.z * hb.z + w.w * hb.w;
                a1b += w2.x * hb2.x + w2.y * hb2.y + w2.z * hb2.z + w2.w * hb2.w;
            }
            s_g0p[khalf][r] = a0 + a0b;
            s_g0p[khalf][128 + r] = a1 + a1b;
        }
        __syncthreads();

        // ===== deferred wait on h1(t-1)+mask; head(t-1); break check =====
        if (t > 0) {
            mbar_wait_parity(barH1_l, (uint32_t)((t - 1) & 1));
            int sl = (t - 1) & 1;
            if (tid < 5) {
                int n = (int)rank * 5 + tid;
                int band = n % NB, b = n / NB;
                float a = s_boutv[tid];
                #pragma unroll 8
                for (int j = 0; j < 128; j++)
                    a += s_wout[(tid << 7) + j] * s_h1[sl][b * 128 + j];
                out[(size_t)b * T_STEPS * NB + (size_t)(t - 1) * NB + band] = a;
            }
            if (t == T_STEPS) break;
            int mdet = s_mslot[sl][0] & s_mslot[sl][1] & s_mslot[sl][2] & s_mslot[sl][3];
            if (t > 10 && mdet) {
                per = (mdet & 1) ? 1 : ((mdet & 2) ? 2 : ((mdet & 4) ? 3 : 4));
                td = t;
                break;
            }
        }

        // ===== cell 0 + h0 exchange (writers = tid<64) =====
        float h0v = 0.f;
        if (tid < 64) {
            int base = wb * 128 + wu;
            float gi = s_g0p[0][base]       + s_g0p[1][base];
            float gf = s_g0p[0][base + 32]  + s_g0p[1][base + 32];
            float gg = s_g0p[0][base + 64]  + s_g0p[1][base + 64];
            float go = s_g0p[0][base + 96]  + s_g0p[1][base + 96];
            c0r = sigm(gf) * c0r + sigm(gi) * tanhx(gg);
            h0v = sigm(go) * tanhx(c0r);
            int sl = t & 1;
            #pragma unroll
            for (int rr = 0; rr < 4; rr++) st_cluster_f32(rh0[sl][rr], h0v);
            #pragma unroll
            for (int rr = 0; rr < 4; rr++) mbar_arrive_cluster(rb0[rr]);
        }

        // ===== layer 1 gates: khalf1 on h1(t-1) w/o wait; khalf0 waits h0(t) =====
        if (khalf == 1) {
            const float* h = s_h1[(t + 1) & 1];
            float a0 = 0.f, a0b = 0.f, a1 = 0.f, a1b = 0.f;
            #pragma unroll 8
            for (int k4 = 0; k4 < 32; k4 += 2) {
                float4 w  = g_whh1_t[(k4 << 9) + grow];
                float4 w2 = g_whh1_t[((k4 + 1) << 9) + grow];
                float4 ha  = *(const float4*)(h + (k4 << 2));
                float4 ha2 = *(const float4*)(h + ((k4 + 1) << 2));
                float4 hb  = *(const float4*)(h + 128 + (k4 << 2));
                float4 hb2 = *(const float4*)(h + 128 + ((k4 + 1) << 2));
                a0  += w.x * ha.x + w.y * ha.y + w.z * ha.z + w.w * ha.w;
                a0b += w2.x * ha2.x + w2.y * ha2.y + w2.z * ha2.z + w2.w * ha2.w;
                a1  += w.x * hb.x + w.y * hb.y + w.z * hb.z + w.w * hb.w;
                a1b += w2.x * hb2.x + w2.y * hb2.y + w2.z * hb2.z + w2.w * hb2.w;
            }
            s_g1p[1][r] = a0 + a0b;
            s_g1p[1][128 + r] = a1 + a1b;
        } else {
            mbar_wait_parity(barH0_l, (uint32_t)(t & 1));
            const float* h = s_h0[t & 1];
            // BUGFIX (R4): bias must seed BOTH batches, not just batch 0.
            float a0 = s_b1[r], a0b = 0.f, a1 = s_b1[r], a1b = 0.f;
            #pragma unroll 8
            for (int k4 = 0; k4 < 32; k4 += 2) {
                float4 w  = g_wih1_t[(k4 << 9) + grow];
                float4 w2 = g_wih1_t[((k4 + 1) << 9) + grow];
                float4 ha  = *(const float4*)(h + (k4 << 2));
                float4 ha2 = *(const float4*)(h + ((k4 + 1) << 2));
                float4 hb  = *(const float4*)(h + 128 + (k4 << 2));
                float4 hb2 = *(const float4*)(h + 128 + ((k4 + 1) << 2));
                a0  += w.x * ha.x + w.y * ha.y + w.z * ha.z + w.w * ha.w;
                a0b += w2.x * ha2.x + w2.y * ha2.y + w2.z * ha2.z + w2.w * ha2.w;
                a1  += w.x * hb.x + w.y * hb.y + w.z * hb.z + w.w * hb.w;
                a1b += w2.x * hb2.x + w2.y * hb2.y + w2.z * hb2.z + w2.w * hb2.w;
            }
            s_g1p[0][r] = a0 + a0b;
            s_g1p[0][128 + r] = a1 + a1b;
        }
        __syncthreads();

        // ===== cell 1 + h1 exchange + epsilon detection =====
        if (tid < 64) {
            int base = wb * 128 + wu;
            float gi = s_g1p[0][base]       + s_g1p[1][base];
            float gf = s_g1p[0][base + 32]  + s_g1p[1][base + 32];
            float gg = s_g1p[0][base + 64]  + s_g1p[1][base + 64];
            float go = s_g1p[0][base + 96]  + s_g1p[1][base + 96];
            c1r = sigm(gf) * c1r + sigm(gi) * tanhx(gg);
            float h1v = sigm(go) * tanhx(c1r);
            int sl = t & 1;
            #pragma unroll
            for (int rr = 0; rr < 4; rr++) st_cluster_f32(rh1[sl][rr], h1v);
            int m = 0;
            #pragma unroll
            for (int p = 1; p <= 4; p++) {
                int hs = (t - p) & 3;
                int e = (fabsf(h0v - hist[hs][0]) <= EPS_DET) &&
                        (fabsf(c0r - hist[hs][1]) <= EPS_DET) &&
                        (fabsf(h1v - hist[hs][2]) <= EPS_DET) &&
                        (fabsf(c1r - hist[hs][3]) <= EPS_DET);
                m |= e << (p - 1);
            }
            int ts = t & 3;
            hist[ts][0] = h0v; hist[ts][1] = c0r; hist[ts][2] = h1v; hist[ts][3] = c1r;
            m = __reduce_and_sync(0xFFFFFFFFu, m);
            if ((tid & 31) == 0 && m != 0xF) atomicAnd(&s_lmask[t & 1], m);
            #pragma unroll
            for (int rr = 0; rr < 4; rr++) mbar_arrive_cluster(rb1[rr]);
            asm volatile("bar.sync 1, 64;" ::: "memory");
            if (tid == 0) {
                uint32_t mv = (uint32_t)s_lmask[t & 1];
                #pragma unroll
                for (int rr = 0; rr < 4; rr++) st_cluster_u32(rmk[t & 1][rr], mv);
                #pragma unroll
                for (int rr = 0; rr < 4; rr++) mbar_arrive_cluster(rb1[rr]);
            }
        }
    }

    cluster_sync_all();
    if (rank == 0 && tid == 0) { g_fix[0] = td; g_fix[1] = per; }
}

// ---------------- parallel periodic tail fill (float2) ----------------
__global__ void k_fill(float* __restrict__ out) {
    int td = g_fix[0], p = g_fix[1];
    int idx = blockIdx.x * blockDim.x + threadIdx.x;
    if (idx >= NOUT / 2) return;
    int k2 = idx % 5;
    int rr = idx / 5;
    int t = rr % T_STEPS;
    int b = rr / T_STEPS;
    if (t < td) return;
    int src = td - p + ((t - td) % p);
    float2* o2 = (float2*)out;
    o2[idx] = o2[((size_t)b * T_STEPS + src) * 5 + k2];
}

// ---------------- launch ----------------
extern "C" void kernel_launch(void* const* d_in, const int* in_sizes, int n_in,
                              void* d_out, int out_size) {
    const float* x     = (const float*)d_in[0];
    const float* w1    = (const float*)d_in[1];
    const float* b1    = (const float*)d_in[2];
    const float* w2    = (const float*)d_in[3];
    const float* b2    = (const float*)d_in[4];
    const float* w_ih0 = (const float*)d_in[5];
    const float* w_hh0 = (const float*)d_in[6];
    const float* b_ih0 = (const float*)d_in[7];
    const float* b_hh0 = (const float*)d_in[8];
    const float* w_ih1 = (const float*)d_in[9];
    const float* w_hh1 = (const float*)d_in[10];
    const float* b_ih1 = (const float*)d_in[11];
    const float* b_hh1 = (const float*)d_in[12];
    const float* w_out = (const float*)d_in[13];
    const float* b_out = (const float*)d_in[14];
    float* out = (float*)d_out;

    k_transpose<<<256, 256>>>(w_hh0, w_ih1, w_hh1, w_ih0);
    k_seq<<<CLUSTER_N, THREADS>>>(x, w1, b1, w2, b2,
                                  b_ih0, b_hh0, b_ih1, b_hh1, w_out, b_out, out);
    k_fill<<<(NOUT / 2 + 255) / 256, 256>>>(out);
}

// round 6
// speedup vs baseline: 10529.9565x; 1.4615x over previous
#include <cuda_runtime.h>
#include <math.h>
#include <stdint.h>

#define T_STEPS 144000
#define NB 10
#define NOUT (2*T_STEPS*NB)
#define EPS_DET 2e-5f
#define CLUSTER_N 4
#define THREADS 256

// ---------------- device scratch ----------------
__device__ float4 g_whh0_t[32*512];   // [k4][g]
__device__ float4 g_wih1_t[32*512];
__device__ float4 g_whh1_t[32*512];
__device__ int    g_fix[2];           // {t_detect, period}

// ---------------- PTX helpers ----------------
__device__ __forceinline__ uint32_t smem_u32(const void* p) {
    uint32_t a;
    asm("{ .reg .u64 t; cvta.to.shared.u64 t, %1; cvt.u32.u64 %0, t; }" : "=r"(a) : "l"(p));
    return a;
}
__device__ __forceinline__ uint32_t mapa_rank(uint32_t local, uint32_t rank) {
    uint32_t r;
    asm("mapa.shared::cluster.u32 %0, %1, %2;" : "=r"(r) : "r"(local), "r"(rank));
    return r;
}
__device__ __forceinline__ void st_cluster_f32(uint32_t addr, float v) {
    asm volatile("st.shared::cluster.f32 [%0], %1;" :: "r"(addr), "f"(v) : "memory");
}
__device__ __forceinline__ void st_cluster_u32(uint32_t addr, uint32_t v) {
    asm volatile("st.shared::cluster.u32 [%0], %1;" :: "r"(addr), "r"(v) : "memory");
}
__device__ __forceinline__ void mbar_init(uint32_t addr, uint32_t cnt) {
    asm volatile("mbarrier.init.shared.b64 [%0], %1;" :: "r"(addr), "r"(cnt) : "memory");
}
__device__ __forceinline__ void mbar_arrive_cluster(uint32_t addr) {
    asm volatile("mbarrier.arrive.release.cluster.shared::cluster.b64 _, [%0];"
                 :: "r"(addr) : "memory");
}
__device__ __forceinline__ void mbar_wait_parity(uint32_t addr, uint32_t parity) {
    asm volatile(
        "{\n\t.reg .pred P;\n\t"
        "WLP_%=:\n\t"
        "mbarrier.try_wait.parity.acquire.cluster.shared::cta.b64 P, [%0], %1, 0x989680;\n\t"
        "@P bra.uni WDN_%=;\n\t"
        "bra.uni WLP_%=;\n\t"
        "WDN_%=:\n\t}"
        :: "r"(addr), "r"(parity) : "memory");
}
__device__ __forceinline__ void cluster_sync_all() {
    asm volatile("barrier.cluster.arrive.aligned;" ::: "memory");
    asm volatile("barrier.cluster.wait.aligned;" ::: "memory");
}
__device__ __forceinline__ uint32_t ctarank() {
    uint32_t r; asm("mov.u32 %0, %%cluster_ctarank;" : "=r"(r)); return r;
}
// fast gates: MUFU-based, rel err ~1e-6
__device__ __forceinline__ float ex2a(float x) { float r; asm("ex2.approx.f32 %0, %1;" : "=f"(r) : "f"(x)); return r; }
__device__ __forceinline__ float rcpa(float x) { float r; asm("rcp.approx.f32 %0, %1;" : "=f"(r) : "f"(x)); return r; }
__device__ __forceinline__ float sigm(float v)  { return rcpa(1.0f + ex2a(-1.4426950408889634f * v)); }
__device__ __forceinline__ float tanhx(float v) { return 1.0f - 2.0f * rcpa(1.0f + ex2a(2.8853900817779268f * v)); }

// ---------------- clustered sequential kernel ----------------
__global__ void __launch_bounds__(THREADS, 1) __cluster_dims__(CLUSTER_N, 1, 1)
k_seq(const float* __restrict__ x,
      const float* __restrict__ w1e,  const float* __restrict__ eb1,
      const float* __restrict__ w2e,  const float* __restrict__ eb2,
      const float* __restrict__ wih0,
      const float* __restrict__ bih0, const float* __restrict__ bhh0,
      const float* __restrict__ whh0,
      const float* __restrict__ wih1, const float* __restrict__ whh1,
      const float* __restrict__ bih1, const float* __restrict__ bhh1,
      const float* __restrict__ wout, const float* __restrict__ bout,
      float* __restrict__ out) {
    __shared__ __align__(16) float s_h0[2][256];   // [slot][b*128 + unit]
    __shared__ __align__(16) float s_h1[2][256];
    __shared__ float s_g0p[2][256];                // [khalf][b*128 + r]
    __shared__ float s_g1p[2][256];
    __shared__ float s_xp0[256];                   // [b*128 + r]
    __shared__ float s_b1[128];
    __shared__ __align__(16) float s_wout[5*128];
    __shared__ float s_boutv[8];
    __shared__ float s_l1[128];
    __shared__ __align__(16) float s_l2[256];
    __shared__ int   s_lmask[2];
    __shared__ int   s_mslot[2][4];                // [slot][src rank]
    __shared__ __align__(8) unsigned long long s_barH0, s_barH1;

    const int tid = threadIdx.x;
    const uint32_t rank = ctarank();
    const int r = tid & 127;
    const int khalf = tid >> 7;
    const int wi = tid >> 5;
    const int lane = tid & 31;
    const int grow = ((r >> 5) << 7) + (int)(rank << 5) + (r & 31);  // global gate row

    // ---- prologue: transpose this CTA's weight slices into [k4][g] ----
    {
        const float4* src0 = (const float4*)whh0;
        const float4* src1 = (const float4*)wih1;
        const float4* src2 = (const float4*)whh1;
        for (int idx = tid; idx < 4096; idx += THREADS) {
            int k4 = idx >> 7;            // 0..31
            int row = idx & 127;          // local row
            int g = ((row >> 5) << 7) + (int)(rank << 5) + (row & 31);
            g_whh0_t[(k4 << 9) + g] = src0[g * 32 + k4];
            g_wih1_t[(k4 << 9) + g] = src1[g * 32 + k4];
            g_whh1_t[(k4 << 9) + g] = src2[g * 32 + k4];
        }
    }

    // ---- encoder MLP (redundant per CTA) ----
    if (tid < 128) { int b = tid >> 6, j = tid & 63;
        float a = eb1[j];
        #pragma unroll
        for (int k = 0; k < 16; k++) a += x[b * 16 + k] * w1e[j * 16 + k];
        s_l1[b * 64 + j] = fmaxf(a, 0.f);
    }
    __syncthreads();
    { int b = tid >> 7, j = tid & 127;
        float a = eb2[j];
        #pragma unroll 8
        for (int k = 0; k < 64; k++) a += s_l1[b * 64 + k] * w2e[j * 64 + k];
        s_l2[b * 128 + j] = fmaxf(a, 0.f);
    }
    __syncthreads();
    { int b = tid >> 7;
        float a = bih0[grow] + bhh0[grow];
        const float4* l2v = (const float4*)(s_l2 + b * 128);
        const float4* w0v = (const float4*)wih0;
        #pragma unroll 8
        for (int k4 = 0; k4 < 32; k4++) {
            float4 w = w0v[grow * 32 + k4];
            float4 l = l2v[k4];
            a += w.x * l.x + w.y * l.y + w.z * l.z + w.w * l.w;
        }
        s_xp0[b * 128 + r] = a;
    }
    if (tid < 128) s_b1[tid] = bih1[grow] + bhh1[grow];
    for (int idx = tid; idx < 5 * 128; idx += THREADS) {
        int i = idx >> 7, j = idx & 127;
        int band = ((int)rank * 5 + i) % NB;
        s_wout[idx] = wout[band * 128 + j];
    }
    if (tid < 5) s_boutv[tid] = bout[((int)rank * 5 + tid) % NB];
    { s_h0[0][tid] = 0.f; s_h0[1][tid] = 0.f; s_h1[0][tid] = 0.f; s_h1[1][tid] = 0.f; }
    if (tid < 2) s_lmask[tid] = 0xF;
    if (tid < 8) s_mslot[tid >> 2][tid & 3] = 0xF;
    if (tid == 0) {
        mbar_init(smem_u32(&s_barH0), CLUSTER_N);   // 1 aggregated arrive per source CTA
        mbar_init(smem_u32(&s_barH1), CLUSTER_N);
    }
    __syncthreads();
    cluster_sync_all();

    const uint32_t barH0_l = smem_u32(&s_barH0);
    const uint32_t barH1_l = smem_u32(&s_barH1);
    uint32_t rb0[4], rb1[4], rh0[2][4], rh1[2][4], rmk[2][4];
    float c0r = 0.f, c1r = 0.f;
    float hist[4][4];
    const int wb = tid >> 5, wu = tid & 31;
    if (tid < 64) {
        int off = wb * 128 + (int)(rank << 5) + wu;
        #pragma unroll
        for (int rr = 0; rr < 4; rr++) {
            rb0[rr] = mapa_rank(barH0_l, rr);
            rb1[rr] = mapa_rank(barH1_l, rr);
            rh0[0][rr] = mapa_rank(smem_u32(&s_h0[0][off]), rr);
            rh0[1][rr] = mapa_rank(smem_u32(&s_h0[1][off]), rr);
            rh1[0][rr] = mapa_rank(smem_u32(&s_h1[0][off]), rr);
            rh1[1][rr] = mapa_rank(smem_u32(&s_h1[1][off]), rr);
        }
        #pragma unroll
        for (int p = 0; p < 4; p++)
            #pragma unroll
            for (int i = 0; i < 4; i++) hist[p][i] = 1e30f;
    }
    if (tid == 0) {
        #pragma unroll
        for (int rr = 0; rr < 4; rr++) {
            rmk[0][rr] = mapa_rank(smem_u32(&s_mslot[0][rank]), rr);
            rmk[1][rr] = mapa_rank(smem_u32(&s_mslot[1][rank]), rr);
        }
    }

    int td = T_STEPS, per = 1;

    for (int t = 0; t <= T_STEPS; t++) {
        if (tid == 0) s_lmask[t & 1] = 0xF;

        // ===== layer 0 gates (h0(t-1); guarded by barH0(t-1) acquired last step) =====
        {
            const float* h = s_h0[(t + 1) & 1];
            float a0 = 0.f, a0b = 0.f, a1 = 0.f, a1b = 0.f;
            if (khalf == 0) { a0 = s_xp0[r]; a1 = s_xp0[128 + r]; }
            int k4lo = khalf << 4;
            #pragma unroll
            for (int k4 = 0; k4 < 16; k4 += 2) {
                float4 w  = g_whh0_t[((k4lo + k4) << 9) + grow];
                float4 w2 = g_whh0_t[((k4lo + k4 + 1) << 9) + grow];
                float4 ha  = *(const float4*)(h + ((k4lo + k4) << 2));
                float4 ha2 = *(const float4*)(h + ((k4lo + k4 + 1) << 2));
                float4 hb  = *(const float4*)(h + 128 + ((k4lo + k4) << 2));
                float4 hb2 = *(const float4*)(h + 128 + ((k4lo + k4 + 1) << 2));
                a0  += w.x * ha.x + w.y * ha.y + w.z * ha.z + w.w * ha.w;
                a0b += w2.x * ha2.x + w2.y * ha2.y + w2.z * ha2.z + w2.w * ha2.w;
                a1  += w.x * hb.x + w.y * hb.y + w.z * hb.z + w.w * hb.w;
                a1b += w2.x * hb2.x + w2.y * hb2.y + w2.z * hb2.z + w2.w * hb2.w;
            }
            s_g0p[khalf][r] = a0 + a0b;
            s_g0p[khalf][128 + r] = a1 + a1b;
        }

        // ===== wait h1(t-1)+mask; break check (uniform) =====
        if (t > 0) {
            mbar_wait_parity(barH1_l, (uint32_t)((t - 1) & 1));
            int sl = (t - 1) & 1;
            int mdet = s_mslot[sl][0] & s_mslot[sl][1] & s_mslot[sl][2] & s_mslot[sl][3];
            bool brk = (t == T_STEPS) || (t > 10 && mdet != 0);
            if (brk) {
                // final head for step t-1 (warps 2-6)
                if (wi >= 2 && wi < 7) {
                    int i = wi - 2;
                    int n = (int)rank * 5 + i; int band = n % NB, b = n / NB;
                    float4 hv = *(const float4*)(&s_h1[sl][b * 128 + lane * 4]);
                    float4 wv = *(const float4*)(&s_wout[i * 128 + lane * 4]);
                    float a = hv.x * wv.x + hv.y * wv.y + hv.z * wv.z + hv.w * wv.w;
                    a += __shfl_xor_sync(0xffffffffu, a, 16);
                    a += __shfl_xor_sync(0xffffffffu, a, 8);
                    a += __shfl_xor_sync(0xffffffffu, a, 4);
                    a += __shfl_xor_sync(0xffffffffu, a, 2);
                    a += __shfl_xor_sync(0xffffffffu, a, 1);
                    if (lane == 0)
                        out[(size_t)b * T_STEPS * NB + (size_t)(t - 1) * NB + band] = a + s_boutv[i];
                }
                if (t < T_STEPS) {
                    per = (mdet & 1) ? 1 : ((mdet & 2) ? 2 : ((mdet & 4) ? 3 : 4));
                    td = t;
                }
                break;
            }
        }
        __syncthreads();   // s_g0p ready for cell0

        // ===== cell0 (warps 0-1)  ||  head(t-1) (warps 2-6) =====
        float h0v = 0.f;
        if (tid < 64) {
            int base = wb * 128 + wu;
            float gi = s_g0p[0][base]       + s_g0p[1][base];
            float gf = s_g0p[0][base + 32]  + s_g0p[1][base + 32];
            float gg = s_g0p[0][base + 64]  + s_g0p[1][base + 64];
            float go = s_g0p[0][base + 96]  + s_g0p[1][base + 96];
            c0r = sigm(gf) * c0r + sigm(gi) * tanhx(gg);
            h0v = sigm(go) * tanhx(c0r);
            int sl = t & 1;
            #pragma unroll
            for (int rr = 0; rr < 4; rr++) st_cluster_f32(rh0[sl][rr], h0v);
            asm volatile("bar.sync 2, 64;" ::: "memory");      // order all writers' stores
            if (tid < 4) mbar_arrive_cluster(rb0[tid]);        // 1 arrive per target CTA
        } else if (t > 0 && wi >= 2 && wi < 7) {
            int sl = (t - 1) & 1;
            int i = wi - 2;
            int n = (int)rank * 5 + i; int band = n % NB, b = n / NB;
            float4 hv = *(const float4*)(&s_h1[sl][b * 128 + lane * 4]);
            float4 wv = *(const float4*)(&s_wout[i * 128 + lane * 4]);
            float a = hv.x * wv.x + hv.y * wv.y + hv.z * wv.z + hv.w * wv.w;
            a += __shfl_xor_sync(0xffffffffu, a, 16);
            a += __shfl_xor_sync(0xffffffffu, a, 8);
            a += __shfl_xor_sync(0xffffffffu, a, 4);
            a += __shfl_xor_sync(0xffffffffu, a, 2);
            a += __shfl_xor_sync(0xffffffffu, a, 1);
            if (lane == 0)
                out[(size_t)b * T_STEPS * NB + (size_t)(t - 1) * NB + band] = a + s_boutv[i];
        }

        // ===== layer 1 gates: whh1 part first (hides exchange), then wait, then wih1 =====
        {
            float a0, a1, a0b = 0.f, a1b = 0.f;
            if (khalf == 0) { a0 = s_b1[r]; a1 = s_b1[r]; } else { a0 = 0.f; a1 = 0.f; }
            int k4lo = khalf << 4;
            {
                const float* h = s_h1[(t + 1) & 1];     // h1(t-1)
                #pragma unroll
                for (int k4 = 0; k4 < 16; k4 += 2) {
                    float4 w  = g_whh1_t[((k4lo + k4) << 9) + grow];
                    float4 w2 = g_whh1_t[((k4lo + k4 + 1) << 9) + grow];
                    float4 ha  = *(const float4*)(h + ((k4lo + k4) << 2));
                    float4 ha2 = *(const float4*)(h + ((k4lo + k4 + 1) << 2));
                    float4 hb  = *(const float4*)(h + 128 + ((k4lo + k4) << 2));
                    float4 hb2 = *(const float4*)(h + 128 + ((k4lo + k4 + 1) << 2));
                    a0  += w.x * ha.x + w.y * ha.y + w.z * ha.z + w.w * ha.w;
                    a0b += w2.x * ha2.x + w2.y * ha2.y + w2.z * ha2.z + w2.w * ha2.w;
                    a1  += w.x * hb.x + w.y * hb.y + w.z * hb.z + w.w * hb.w;
                    a1b += w2.x * hb2.x + w2.y * hb2.y + w2.z * hb2.z + w2.w * hb2.w;
                }
            }
            mbar_wait_parity(barH0_l, (uint32_t)(t & 1));
            {
                const float* h = s_h0[t & 1];           // h0(t)
                #pragma unroll
                for (int k4 = 0; k4 < 16; k4 += 2) {
                    float4 w  = g_wih1_t[((k4lo + k4) << 9) + grow];
                    float4 w2 = g_wih1_t[((k4lo + k4 + 1) << 9) + grow];
                    float4 ha  = *(const float4*)(h + ((k4lo + k4) << 2));
                    float4 ha2 = *(const float4*)(h + ((k4lo + k4 + 1) << 2));
                    float4 hb  = *(const float4*)(h + 128 + ((k4lo + k4) << 2));
                    float4 hb2 = *(const float4*)(h + 128 + ((k4lo + k4 + 1) << 2));
                    a0  += w.x * ha.x + w.y * ha.y + w.z * ha.z + w.w * ha.w;
                    a0b += w2.x * ha2.x + w2.y * ha2.y + w2.z * ha2.z + w2.w * ha2.w;
                    a1  += w.x * hb.x + w.y * hb.y + w.z * hb.z + w.w * hb.w;
                    a1b += w2.x * hb2.x + w2.y * hb2.y + w2.z * hb2.z + w2.w * hb2.w;
                }
            }
            s_g1p[khalf][r] = a0 + a0b;
            s_g1p[khalf][128 + r] = a1 + a1b;
        }
        __syncthreads();

        // ===== cell1 + h1 exchange + epsilon detection =====
        if (tid < 64) {
            int base = wb * 128 + wu;
            float gi = s_g1p[0][base]       + s_g1p[1][base];
            float gf = s_g1p[0][base + 32]  + s_g1p[1][base + 32];
            float gg = s_g1p[0][base + 64]  + s_g1p[1][base + 64];
            float go = s_g1p[0][base + 96]  + s_g1p[1][base + 96];
            c1r = sigm(gf) * c1r + sigm(gi) * tanhx(gg);
            float h1v = sigm(go) * tanhx(c1r);
            int sl = t & 1;
            #pragma unroll
            for (int rr = 0; rr < 4; rr++) st_cluster_f32(rh1[sl][rr], h1v);
            int m = 0;
            #pragma unroll
            for (int p = 1; p <= 4; p++) {
                int hs = (t - p) & 3;
                int e = (fabsf(h0v - hist[hs][0]) <= EPS_DET) &&
                        (fabsf(c0r - hist[hs][1]) <= EPS_DET) &&
                        (fabsf(h1v - hist[hs][2]) <= EPS_DET) &&
                        (fabsf(c1r - hist[hs][3]) <= EPS_DET);
                m |= e << (p - 1);
            }
            int ts = t & 3;
            hist[ts][0] = h0v; hist[ts][1] = c0r; hist[ts][2] = h1v; hist[ts][3] = c1r;
            m = __reduce_and_sync(0xFFFFFFFFu, m);
            if ((tid & 31) == 0 && m != 0xF) atomicAnd(&s_lmask[t & 1], m);
            asm volatile("bar.sync 1, 64;" ::: "memory");   // order stores + mask ANDs
            if (tid == 0) {
                uint32_t mv = (uint32_t)s_lmask[t & 1];
                #pragma unroll
                for (int rr = 0; rr < 4; rr++) st_cluster_u32(rmk[t & 1][rr], mv);
                #pragma unroll
                for (int rr = 0; rr < 4; rr++) mbar_arrive_cluster(rb1[rr]);
            }
        }
    }

    cluster_sync_all();
    if (rank == 0 && tid == 0) { g_fix[0] = td; g_fix[1] = per; }
}

// ---------------- parallel periodic tail fill from SMEM pattern table ----------------
__global__ void k_fill(float* __restrict__ out) {
    __shared__ float s_pat[2][4][10];
    int td = g_fix[0], p = g_fix[1];
    int tt = threadIdx.x;
    if (tt < 80) {
        int b = tt / 40, rr = tt % 40, pp = rr / 10, k = rr % 10;
        int src = td - p + (pp % p);
        s_pat[b][pp][k] = out[((size_t)b * T_STEPS + src) * NB + k];
    }
    __syncthreads();
    int idx = blockIdx.x * blockDim.x + threadIdx.x;
    if (idx >= NOUT / 2) return;
    int k2 = idx % 5;
    int rr = idx / 5;
    int t  = rr % T_STEPS;
    int b  = rr / T_STEPS;
    if (t < td) return;
    int q = t - td;
    int pp = q - (q / p) * p;
    float2 v;
    v.x = s_pat[b][pp][k2 * 2];
    v.y = s_pat[b][pp][k2 * 2 + 1];
    reinterpret_cast<float2*>(out)[idx] = v;
}

// ---------------- launch ----------------
extern "C" void kernel_launch(void* const* d_in, const int* in_sizes, int n_in,
                              void* d_out, int out_size) {
    const float* x     = (const float*)d_in[0];
    const float* w1    = (const float*)d_in[1];
    const float* b1    = (const float*)d_in[2];
    const float* w2    = (const float*)d_in[3];
    const float* b2    = (const float*)d_in[4];
    const float* w_ih0 = (const float*)d_in[5];
    const float* w_hh0 = (const float*)d_in[6];
    const float* b_ih0 = (const float*)d_in[7];
    const float* b_hh0 = (const float*)d_in[8];
    const float* w_ih1 = (const float*)d_in[9];
    const float* w_hh1 = (const float*)d_in[10];
    const float* b_ih1 = (const float*)d_in[11];
    const float* b_hh1 = (const float*)d_in[12];
    const float* w_out = (const float*)d_in[13];
    const float* b_out = (const float*)d_in[14];
    float* out = (float*)d_out;

    k_seq<<<CLUSTER_N, THREADS>>>(x, w1, b1, w2, b2, w_ih0,
                                  b_ih0, b_hh0, w_hh0,
                                  w_ih1, w_hh1, b_ih1, b_hh1, w_out, b_out, out);
    k_fill<<<(NOUT / 2 + 255) / 256, 256>>>(out);
}

// round 7
// speedup vs baseline: 13593.9505x; 1.2910x over previous
#include <cuda_runtime.h>
#include <math.h>
#include <stdint.h>

#define T_STEPS 144000
#define NB 10
#define NOUT (2*T_STEPS*NB)
#define EPS_DET 1e-4f
#define CLUSTER_N 8
#define THREADS 256

// ---------------- device scratch ----------------
__device__ float4 g_whh0_t[32*512];   // [k4][g]
__device__ float4 g_wih1_t[32*512];
__device__ float4 g_whh1_t[32*512];
__device__ int    g_fix[2];           // {t_detect, period}

// ---------------- PTX helpers ----------------
__device__ __forceinline__ uint32_t smem_u32(const void* p) {
    uint32_t a;
    asm("{ .reg .u64 t; cvta.to.shared.u64 t, %1; cvt.u32.u64 %0, t; }" : "=r"(a) : "l"(p));
    return a;
}
__device__ __forceinline__ uint32_t mapa_rank(uint32_t local, uint32_t rank) {
    uint32_t r;
    asm("mapa.shared::cluster.u32 %0, %1, %2;" : "=r"(r) : "r"(local), "r"(rank));
    return r;
}
__device__ __forceinline__ void st_cluster_f32(uint32_t addr, float v) {
    asm volatile("st.shared::cluster.f32 [%0], %1;" :: "r"(addr), "f"(v) : "memory");
}
__device__ __forceinline__ void st_cluster_u32(uint32_t addr, uint32_t v) {
    asm volatile("st.shared::cluster.u32 [%0], %1;" :: "r"(addr), "r"(v) : "memory");
}
__device__ __forceinline__ void mbar_init(uint32_t addr, uint32_t cnt) {
    asm volatile("mbarrier.init.shared.b64 [%0], %1;" :: "r"(addr), "r"(cnt) : "memory");
}
__device__ __forceinline__ void mbar_arrive_cluster(uint32_t addr) {
    asm volatile("mbarrier.arrive.release.cluster.shared::cluster.b64 _, [%0];"
                 :: "r"(addr) : "memory");
}
__device__ __forceinline__ void mbar_wait_parity(uint32_t addr, uint32_t parity) {
    asm volatile(
        "{\n\t.reg .pred P;\n\t"
        "WLP_%=:\n\t"
        "mbarrier.try_wait.parity.acquire.cluster.shared::cta.b64 P, [%0], %1, 0x989680;\n\t"
        "@P bra.uni WDN_%=;\n\t"
        "bra.uni WLP_%=;\n\t"
        "WDN_%=:\n\t}"
        :: "r"(addr), "r"(parity) : "memory");
}
__device__ __forceinline__ void cluster_sync_all() {
    asm volatile("barrier.cluster.arrive.aligned;" ::: "memory");
    asm volatile("barrier.cluster.wait.aligned;" ::: "memory");
}
__device__ __forceinline__ uint32_t ctarank() {
    uint32_t r; asm("mov.u32 %0, %%cluster_ctarank;" : "=r"(r)); return r;
}
// fast gates: MUFU-based, rel err ~1e-6
__device__ __forceinline__ float ex2a(float x) { float r; asm("ex2.approx.f32 %0, %1;" : "=f"(r) : "f"(x)); return r; }
__device__ __forceinline__ float rcpa(float x) { float r; asm("rcp.approx.f32 %0, %1;" : "=f"(r) : "f"(x)); return r; }
__device__ __forceinline__ float sigm(float v)  { return rcpa(1.0f + ex2a(-1.4426950408889634f * v)); }
__device__ __forceinline__ float tanhx(float v) { return 1.0f - 2.0f * rcpa(1.0f + ex2a(2.8853900817779268f * v)); }

// ---------------- clustered sequential kernel (batch-split, 8 CTAs) ----------------
__global__ void __launch_bounds__(THREADS, 1) __cluster_dims__(CLUSTER_N, 1, 1)
k_seq(const float* __restrict__ x,
      const float* __restrict__ w1e,  const float* __restrict__ eb1,
      const float* __restrict__ w2e,  const float* __restrict__ eb2,
      const float* __restrict__ wih0,
      const float* __restrict__ bih0, const float* __restrict__ bhh0,
      const float* __restrict__ whh0,
      const float* __restrict__ wih1, const float* __restrict__ whh1,
      const float* __restrict__ bih1, const float* __restrict__ bhh1,
      const float* __restrict__ wout, const float* __restrict__ bout,
      float* __restrict__ out) {
    __shared__ __align__(16) float s_h0[2][128];   // [slot][unit]  (this CTA's batch)
    __shared__ __align__(16) float s_h1[2][128];
    __shared__ float s_g0p[2][128];                // [khalf][r]
    __shared__ float s_g1p[2][128];
    __shared__ float s_xp0[128];
    __shared__ float s_b1[128];
    __shared__ __align__(16) float s_wout[5*128];
    __shared__ float s_boutv[8];
    __shared__ float s_l1[128];
    __shared__ __align__(16) float s_l2[256];
    __shared__ int   s_mslot[2][8];                // [slot][src rank]
    __shared__ __align__(8) unsigned long long s_barH0, s_barH1;

    const int tid = threadIdx.x;
    const uint32_t rank = ctarank();
    const int g = (int)(rank & 3);                 // quarter within batch group
    const int grpbase = (int)(rank & 4);           // 0 or 4
    const int b_idx = (int)(rank >> 2);            // batch this CTA runs
    const int r = tid & 127;
    const int khalf = tid >> 7;
    const int wi = tid >> 5;
    const int lane = tid & 31;
    const int grow = ((r >> 5) << 7) + (g << 5) + (r & 31);  // global gate row

    // ---- prologue: transpose this CTA's weight slices into [k4][g] ----
    {
        const float4* src0 = (const float4*)whh0;
        const float4* src1 = (const float4*)wih1;
        const float4* src2 = (const float4*)whh1;
        for (int idx = tid; idx < 4096; idx += THREADS) {
            int k4 = idx >> 7;
            int row = idx & 127;
            int gr = ((row >> 5) << 7) + (g << 5) + (row & 31);
            g_whh0_t[(k4 << 9) + gr] = src0[gr * 32 + k4];
            g_wih1_t[(k4 << 9) + gr] = src1[gr * 32 + k4];
            g_whh1_t[(k4 << 9) + gr] = src2[gr * 32 + k4];
        }
    }

    // ---- encoder MLP (redundant per CTA) ----
    if (tid < 128) { int b = tid >> 6, j = tid & 63;
        float a = eb1[j];
        #pragma unroll
        for (int k = 0; k < 16; k++) a += x[b * 16 + k] * w1e[j * 16 + k];
        s_l1[b * 64 + j] = fmaxf(a, 0.f);
    }
    __syncthreads();
    { int b = tid >> 7, j = tid & 127;
        float a = eb2[j];
        #pragma unroll 8
        for (int k = 0; k < 64; k++) a += s_l1[b * 64 + k] * w2e[j * 64 + k];
        s_l2[b * 128 + j] = fmaxf(a, 0.f);
    }
    __syncthreads();
    if (tid < 128) {   // xp0 for THIS batch only
        float a = bih0[grow] + bhh0[grow];
        const float4* l2v = (const float4*)(s_l2 + b_idx * 128);
        const float4* w0v = (const float4*)wih0;
        #pragma unroll 8
        for (int k4 = 0; k4 < 32; k4++) {
            float4 w = w0v[grow * 32 + k4];
            float4 l = l2v[k4];
            a += w.x * l.x + w.y * l.y + w.z * l.z + w.w * l.w;
        }
        s_xp0[r] = a;
        s_b1[r] = bih1[grow] + bhh1[grow];
    }
    // head weights: CTAs with g<2 compute bands g*5+i (i=0..4) for their batch
    for (int idx = tid; idx < 5 * 128; idx += THREADS) {
        int i = idx >> 7, j = idx & 127;
        int band = (g & 1) * 5 + i;
        s_wout[idx] = wout[band * 128 + j];
    }
    if (tid < 5) s_boutv[tid] = bout[(g & 1) * 5 + tid];
    if (tid < 128) { s_h0[0][tid] = 0.f; s_h0[1][tid] = 0.f; s_h1[0][tid] = 0.f; s_h1[1][tid] = 0.f; }
    if (tid < 16) s_mslot[tid >> 3][tid & 7] = 0xF;
    if (tid == 0) {
        mbar_init(smem_u32(&s_barH0), 4);    // 1 aggregated arrive per group CTA
        mbar_init(smem_u32(&s_barH1), 12);   // 4 group h1 + 8 masks
    }
    __syncthreads();
    cluster_sync_all();

    const uint32_t barH0_l = smem_u32(&s_barH0);
    const uint32_t barH1_l = smem_u32(&s_barH1);
    uint32_t rb0[4], rb1g[4], rmb[8], rh0[2][4], rh1[2][4], rmk[2][8];
    float c0r = 0.f, c1r = 0.f;
    float hist[4][4];
    if (tid < 32) {
        int off = (g << 5) + tid;      // unit index within the 128-float h vector
        #pragma unroll
        for (int rr = 0; rr < 4; rr++) {
            rb0[rr]  = mapa_rank(barH0_l, grpbase + rr);
            rb1g[rr] = mapa_rank(barH1_l, grpbase + rr);
            rh0[0][rr] = mapa_rank(smem_u32(&s_h0[0][off]), grpbase + rr);
            rh0[1][rr] = mapa_rank(smem_u32(&s_h0[1][off]), grpbase + rr);
            rh1[0][rr] = mapa_rank(smem_u32(&s_h1[0][off]), grpbase + rr);
            rh1[1][rr] = mapa_rank(smem_u32(&s_h1[1][off]), grpbase + rr);
        }
        #pragma unroll
        for (int rr = 0; rr < 8; rr++) {
            rmb[rr] = mapa_rank(barH1_l, rr);
            rmk[0][rr] = mapa_rank(smem_u32(&s_mslot[0][rank]), rr);
            rmk[1][rr] = mapa_rank(smem_u32(&s_mslot[1][rank]), rr);
        }
        #pragma unroll
        for (int p = 0; p < 4; p++)
            #pragma unroll
            for (int i = 0; i < 4; i++) hist[p][i] = 1e30f;
    }

    int td = T_STEPS, per = 1;

    for (int t = 0; t <= T_STEPS; t++) {
        // ===== layer 0 gates (h0(t-1); slot guarded by protocol) =====
        {
            const float* h = s_h0[(t + 1) & 1];
            float a0 = (khalf == 0) ? s_xp0[r] : 0.f, a0b = 0.f;
            int k4lo = khalf << 4;
            #pragma unroll
            for (int k4 = 0; k4 < 16; k4 += 2) {
                float4 w  = g_whh0_t[((k4lo + k4) << 9) + grow];
                float4 w2 = g_whh0_t[((k4lo + k4 + 1) << 9) + grow];
                float4 ha  = *(const float4*)(h + ((k4lo + k4) << 2));
                float4 ha2 = *(const float4*)(h + ((k4lo + k4 + 1) << 2));
                a0  += w.x * ha.x + w.y * ha.y + w.z * ha.z + w.w * ha.w;
                a0b += w2.x * ha2.x + w2.y * ha2.y + w2.z * ha2.z + w2.w * ha2.w;
            }
            s_g0p[khalf][r] = a0 + a0b;
        }

        // ===== wait h1(t-1)+masks; break check (uniform across all 8 CTAs) =====
        if (t > 0) {
            mbar_wait_parity(barH1_l, (uint32_t)((t - 1) & 1));
            int sl = (t - 1) & 1;
            int mdet = s_mslot[sl][0] & s_mslot[sl][1] & s_mslot[sl][2] & s_mslot[sl][3]
                     & s_mslot[sl][4] & s_mslot[sl][5] & s_mslot[sl][6] & s_mslot[sl][7];
            bool brk = (t == T_STEPS) || (t > 10 && mdet != 0);
            if (brk) {
                if (g < 2 && wi >= 2 && wi < 7) {   // final head for step t-1
                    int i = wi - 2;
                    int band = g * 5 + i;
                    float4 hv = *(const float4*)(&s_h1[sl][lane * 4]);
                    float4 wv = *(const float4*)(&s_wout[i * 128 + lane * 4]);
                    float a = hv.x * wv.x + hv.y * wv.y + hv.z * wv.z + hv.w * wv.w;
                    a += __shfl_xor_sync(0xffffffffu, a, 16);
                    a += __shfl_xor_sync(0xffffffffu, a, 8);
                    a += __shfl_xor_sync(0xffffffffu, a, 4);
                    a += __shfl_xor_sync(0xffffffffu, a, 2);
                    a += __shfl_xor_sync(0xffffffffu, a, 1);
                    if (lane == 0)
                        out[(size_t)b_idx * T_STEPS * NB + (size_t)(t - 1) * NB + band] = a + s_boutv[i];
                }
                if (t < T_STEPS) {
                    per = (mdet & 1) ? 1 : ((mdet & 2) ? 2 : ((mdet & 4) ? 3 : 4));
                    td = t;
                }
                break;
            }
        }
        __syncthreads();   // s_g0p ready for cell0

        // ===== cell0 (warp 0)  ||  head(t-1) (warps 2-6 of g<2 CTAs) =====
        float h0v = 0.f;
        if (tid < 32) {
            float gi = s_g0p[0][tid]      + s_g0p[1][tid];
            float gf = s_g0p[0][tid + 32] + s_g0p[1][tid + 32];
            float gg = s_g0p[0][tid + 64] + s_g0p[1][tid + 64];
            float go = s_g0p[0][tid + 96] + s_g0p[1][tid + 96];
            c0r = sigm(gf) * c0r + sigm(gi) * tanhx(gg);
            h0v = sigm(go) * tanhx(c0r);
            int sl = t & 1;
            #pragma unroll
            for (int rr = 0; rr < 4; rr++) st_cluster_f32(rh0[sl][rr], h0v);
            __syncwarp();
            if (lane < 4) mbar_arrive_cluster(rb0[lane]);
        } else if (t > 0 && g < 2 && wi >= 2 && wi < 7) {
            int sl = (t - 1) & 1;
            int i = wi - 2;
            int band = g * 5 + i;
            float4 hv = *(const float4*)(&s_h1[sl][lane * 4]);
            float4 wv = *(const float4*)(&s_wout[i * 128 + lane * 4]);
            float a = hv.x * wv.x + hv.y * wv.y + hv.z * wv.z + hv.w * wv.w;
            a += __shfl_xor_sync(0xffffffffu, a, 16);
            a += __shfl_xor_sync(0xffffffffu, a, 8);
            a += __shfl_xor_sync(0xffffffffu, a, 4);
            a += __shfl_xor_sync(0xffffffffu, a, 2);
            a += __shfl_xor_sync(0xffffffffu, a, 1);
            if (lane == 0)
                out[(size_t)b_idx * T_STEPS * NB + (size_t)(t - 1) * NB + band] = a + s_boutv[i];
        }

        // ===== layer 1 gates: whh1 first (hides h0 exchange), then wait, then wih1 =====
        {
            float a0 = (khalf == 0) ? s_b1[r] : 0.f, a0b = 0.f;
            int k4lo = khalf << 4;
            {
                const float* h = s_h1[(t + 1) & 1];     // h1(t-1)
                #pragma unroll
                for (int k4 = 0; k4 < 16; k4 += 2) {
                    float4 w  = g_whh1_t[((k4lo + k4) << 9) + grow];
                    float4 w2 = g_whh1_t[((k4lo + k4 + 1) << 9) + grow];
                    float4 ha  = *(const float4*)(h + ((k4lo + k4) << 2));
                    float4 ha2 = *(const float4*)(h + ((k4lo + k4 + 1) << 2));
                    a0  += w.x * ha.x + w.y * ha.y + w.z * ha.z + w.w * ha.w;
                    a0b += w2.x * ha2.x + w2.y * ha2.y + w2.z * ha2.z + w2.w * ha2.w;
                }
            }
            mbar_wait_parity(barH0_l, (uint32_t)(t & 1));
            {
                const float* h = s_h0[t & 1];           // h0(t)
                #pragma unroll
                for (int k4 = 0; k4 < 16; k4 += 2) {
                    float4 w  = g_wih1_t[((k4lo + k4) << 9) + grow];
                    float4 w2 = g_wih1_t[((k4lo + k4 + 1) << 9) + grow];
                    float4 ha  = *(const float4*)(h + ((k4lo + k4) << 2));
                    float4 ha2 = *(const float4*)(h + ((k4lo + k4 + 1) << 2));
                    a0  += w.x * ha.x + w.y * ha.y + w.z * ha.z + w.w * ha.w;
                    a0b += w2.x * ha2.x + w2.y * ha2.y + w2.z * ha2.z + w2.w * ha2.w;
                }
            }
            s_g1p[khalf][r] = a0 + a0b;
        }
        __syncthreads();

        // ===== cell1 + h1 exchange + epsilon detection + mask publish =====
        if (tid < 32) {
            float gi = s_g1p[0][tid]      + s_g1p[1][tid];
            float gf = s_g1p[0][tid + 32] + s_g1p[1][tid + 32];
            float gg = s_g1p[0][tid + 64] + s_g1p[1][tid + 64];
            float go = s_g1p[0][tid + 96] + s_g1p[1][tid + 96];
            c1r = sigm(gf) * c1r + sigm(gi) * tanhx(gg);
            float h1v = sigm(go) * tanhx(c1r);
            int sl = t & 1;
            #pragma unroll
            for (int rr = 0; rr < 4; rr++) st_cluster_f32(rh1[sl][rr], h1v);
            int m = 0;
            #pragma unroll
            for (int p = 1; p <= 4; p++) {
                int hs = (t - p) & 3;
                int e = (fabsf(h0v - hist[hs][0]) <= EPS_DET) &&
                        (fabsf(c0r - hist[hs][1]) <= EPS_DET) &&
                        (fabsf(h1v - hist[hs][2]) <= EPS_DET) &&
                        (fabsf(c1r - hist[hs][3]) <= EPS_DET);
                m |= e << (p - 1);
            }
            int ts = t & 3;
            hist[ts][0] = h0v; hist[ts][1] = c0r; hist[ts][2] = h1v; hist[ts][3] = c1r;
            m = __reduce_and_sync(0xFFFFFFFFu, m);
            __syncwarp();                               // h1 stores complete warp-wide
            if (lane < 4) mbar_arrive_cluster(rb1g[lane]);
            if (lane < 8) {
                st_cluster_u32(rmk[sl][lane], (uint32_t)m);
                mbar_arrive_cluster(rmb[lane]);
            }
        }
    }

    cluster_sync_all();
    if (rank == 0 && tid == 0) { g_fix[0] = td; g_fix[1] = per; }
}

// ---------------- parallel periodic tail fill (float4 stores) ----------------
__global__ void k_fill(float* __restrict__ out) {
    __shared__ float s_pat[2][4][10];
    int td = g_fix[0], p = g_fix[1];
    int tt = threadIdx.x;
    if (tt < 80) {
        int b = tt / 40, rr = tt % 40, pp = rr / 10, k = rr % 10;
        int src = td - p + (pp % p);
        s_pat[b][pp][k] = out[((size_t)b * T_STEPS + src) * NB + k];
    }
    __syncthreads();
    int idx = blockIdx.x * blockDim.x + threadIdx.x;
    if (idx >= NOUT / 4) return;
    const int T10 = T_STEPS * NB;
    int f0 = idx * 4;
    int b  = (f0 >= T10) ? 1 : 0;
    int fb = f0 - b * T10;
    int t0 = fb / 10;
    int k0 = fb - t0 * 10;
    if (t0 + 1 < td) return;     // whole float4 precedes the tail
    float v[4];
    bool  w[4];
    #pragma unroll
    for (int j = 0; j < 4; j++) {
        int k = k0 + j;
        int t = t0;
        if (k >= 10) { k -= 10; t++; }
        if (t >= td) {
            int q = t - td;
            int pp = q - (q / p) * p;
            v[j] = s_pat[b][pp][k];
            w[j] = true;
        } else w[j] = false;
    }
    if (t0 >= td) {
        float4 o; o.x = v[0]; o.y = v[1]; o.z = v[2]; o.w = v[3];
        reinterpret_cast<float4*>(out)[idx] = o;
    } else {
        #pragma unroll
        for (int j = 0; j < 4; j++) if (w[j]) out[f0 + j] = v[j];
    }
}

// ---------------- launch ----------------
extern "C" void kernel_launch(void* const* d_in, const int* in_sizes, int n_in,
                              void* d_out, int out_size) {
    const float* x     = (const float*)d_in[0];
    const float* w1    = (const float*)d_in[1];
    const float* b1    = (const float*)d_in[2];
    const float* w2    = (const float*)d_in[3];
    const float* b2    = (const float*)d_in[4];
    const float* w_ih0 = (const float*)d_in[5];
    const float* w_hh0 = (const float*)d_in[6];
    const float* b_ih0 = (const float*)d_in[7];
    const float* b_hh0 = (const float*)d_in[8];
    const float* w_ih1 = (const float*)d_in[9];
    const float* w_hh1 = (const float*)d_in[10];
    const float* b_ih1 = (const float*)d_in[11];
    const float* b_hh1 = (const float*)d_in[12];
    const float* w_out = (const float*)d_in[13];
    const float* b_out = (const float*)d_in[14];
    float* out = (float*)d_out;

    k_seq<<<CLUSTER_N, THREADS>>>(x, w1, b1, w2, b2, w_ih0,
                                  b_ih0, b_hh0, w_hh0,
                                  w_ih1, w_hh1, b_ih1, b_hh1, w_out, b_out, out);
    k_fill<<<(NOUT / 4 + 255) / 256, 256>>>(out);
}

// round 8
// speedup vs baseline: 21822.3756x; 1.6053x over previous
#include <cuda_runtime.h>
#include <math.h>
#include <stdint.h>

#define T_STEPS 144000
#define NB 10
#define NOUT (2*T_STEPS*NB)
#define T10 (T_STEPS*NB)
#define EPS_DET 1e-4f
#define CLUSTER_N 8
#define THREADS 256

__device__ int g_fix[2];   // {t_detect, period}

// ---------------- PTX helpers ----------------
__device__ __forceinline__ uint32_t smem_u32(const void* p) {
    uint32_t a;
    asm("{ .reg .u64 t; cvta.to.shared.u64 t, %1; cvt.u32.u64 %0, t; }" : "=r"(a) : "l"(p));
    return a;
}
__device__ __forceinline__ uint32_t mapa_rank(uint32_t local, uint32_t rank) {
    uint32_t r;
    asm("mapa.shared::cluster.u32 %0, %1, %2;" : "=r"(r) : "r"(local), "r"(rank));
    return r;
}
__device__ __forceinline__ void st_cluster_f32(uint32_t addr, float v) {
    asm volatile("st.shared::cluster.f32 [%0], %1;" :: "r"(addr), "f"(v) : "memory");
}
__device__ __forceinline__ void st_cluster_u32(uint32_t addr, uint32_t v) {
    asm volatile("st.shared::cluster.u32 [%0], %1;" :: "r"(addr), "r"(v) : "memory");
}
__device__ __forceinline__ void mbar_init(uint32_t addr, uint32_t cnt) {
    asm volatile("mbarrier.init.shared.b64 [%0], %1;" :: "r"(addr), "r"(cnt) : "memory");
}
__device__ __forceinline__ void mbar_arrive_cluster(uint32_t addr) {
    asm volatile("mbarrier.arrive.release.cluster.shared::cluster.b64 _, [%0];"
                 :: "r"(addr) : "memory");
}
__device__ __forceinline__ void mbar_wait_parity(uint32_t addr, uint32_t parity) {
    asm volatile(
        "{\n\t.reg .pred P;\n\t"
        "WLP_%=:\n\t"
        "mbarrier.try_wait.parity.acquire.cluster.shared::cta.b64 P, [%0], %1, 0x989680;\n\t"
        "@P bra.uni WDN_%=;\n\t"
        "bra.uni WLP_%=;\n\t"
        "WDN_%=:\n\t}"
        :: "r"(addr), "r"(parity) : "memory");
}
__device__ __forceinline__ void cluster_sync_all() {
    asm volatile("barrier.cluster.arrive.aligned;" ::: "memory");
    asm volatile("barrier.cluster.wait.aligned;" ::: "memory");
}
__device__ __forceinline__ uint32_t ctarank() {
    uint32_t r; asm("mov.u32 %0, %%cluster_ctarank;" : "=r"(r)); return r;
}
// packed f32x2 fma
__device__ __forceinline__ void fma2(uint64_t& d, uint64_t a, uint64_t b) {
    asm("fma.rn.f32x2 %0, %1, %2, %0;" : "+l"(d) : "l"(a), "l"(b));
}
__device__ __forceinline__ float2 unpk(uint64_t v) {
    float2 r; asm("mov.b64 {%0, %1}, %2;" : "=f"(r.x), "=f"(r.y) : "l"(v)); return r;
}
// fast gates: MUFU-based, rel err ~1e-6
__device__ __forceinline__ float ex2a(float x) { float r; asm("ex2.approx.f32 %0, %1;" : "=f"(r) : "f"(x)); return r; }
__device__ __forceinline__ float rcpa(float x) { float r; asm("rcp.approx.f32 %0, %1;" : "=f"(r) : "f"(x)); return r; }
__device__ __forceinline__ float sigm(float v)  { return rcpa(1.0f + ex2a(-1.4426950408889634f * v)); }
__device__ __forceinline__ float tanhx(float v) { return 1.0f - 2.0f * rcpa(1.0f + ex2a(2.8853900817779268f * v)); }

// ---------------- clustered sequential kernel (batch-split, reg-resident weights) ----------------
__global__ void __launch_bounds__(THREADS, 1) __cluster_dims__(CLUSTER_N, 1, 1)
k_seq(const float* __restrict__ x,
      const float* __restrict__ w1e,  const float* __restrict__ eb1,
      const float* __restrict__ w2e,  const float* __restrict__ eb2,
      const float* __restrict__ wih0,
      const float* __restrict__ bih0, const float* __restrict__ bhh0,
      const float* __restrict__ whh0,
      const float* __restrict__ wih1, const float* __restrict__ whh1,
      const float* __restrict__ bih1, const float* __restrict__ bhh1,
      const float* __restrict__ wout, const float* __restrict__ bout,
      float* __restrict__ out) {
    __shared__ __align__(16) float s_h0[2][128];   // [slot][unit]
    __shared__ __align__(16) float s_h1[2][128];
    __shared__ float s_g0p[2][128];                // [khalf][r]
    __shared__ float s_g1p[2][128];
    __shared__ float s_xp0[128];
    __shared__ float s_b1[128];
    __shared__ __align__(16) float s_wout[5*128];
    __shared__ float s_boutv[8];
    __shared__ float s_l1[128];
    __shared__ __align__(16) float s_l2[256];
    __shared__ int   s_mslot[2][8];                // [slot][src rank]
    __shared__ __align__(8) unsigned long long s_barH0, s_barH1;

    const int tid = threadIdx.x;
    const uint32_t rank = ctarank();
    const int g = (int)(rank & 3);                 // quarter within batch group
    const int grpbase = (int)(rank & 4);           // 0 or 4
    const int b_idx = (int)(rank >> 2);            // batch this CTA runs
    const int r = tid & 127;
    const int khalf = tid >> 7;
    const int wi = tid >> 5;
    const int lane = tid & 31;
    const int grow = ((r >> 5) << 7) + (g << 5) + (r & 31);  // global gate row

    // ---- register-resident weights: this thread's gate rows, its k-half ----
    ulonglong2 w0r[16], w1r[16], wi1r[16];
    {
        const ulonglong2* s0 = (const ulonglong2*)(whh0 + grow * 128 + (khalf << 6));
        const ulonglong2* s1 = (const ulonglong2*)(whh1 + grow * 128 + (khalf << 6));
        const ulonglong2* s2 = (const ulonglong2*)(wih1 + grow * 128 + (khalf << 6));
        #pragma unroll
        for (int i = 0; i < 16; i++) { w0r[i] = s0[i]; w1r[i] = s1[i]; wi1r[i] = s2[i]; }
    }

    // ---- encoder MLP (redundant per CTA) ----
    if (tid < 128) { int b = tid >> 6, j = tid & 63;
        float a = eb1[j];
        #pragma unroll
        for (int k = 0; k < 16; k++) a += x[b * 16 + k] * w1e[j * 16 + k];
        s_l1[b * 64 + j] = fmaxf(a, 0.f);
    }
    __syncthreads();
    { int b = tid >> 7, j = tid & 127;
        float a = eb2[j];
        #pragma unroll 8
        for (int k = 0; k < 64; k++) a += s_l1[b * 64 + k] * w2e[j * 64 + k];
        s_l2[b * 128 + j] = fmaxf(a, 0.f);
    }
    __syncthreads();
    if (tid < 128) {   // xp0 for THIS batch only
        float a = bih0[grow] + bhh0[grow];
        const float4* l2v = (const float4*)(s_l2 + b_idx * 128);
        const float4* w0v = (const float4*)wih0;
        #pragma unroll 8
        for (int k4 = 0; k4 < 32; k4++) {
            float4 w = w0v[grow * 32 + k4];
            float4 l = l2v[k4];
            a += w.x * l.x + w.y * l.y + w.z * l.z + w.w * l.w;
        }
        s_xp0[r] = a;
        s_b1[r] = bih1[grow] + bhh1[grow];
    }
    for (int idx = tid; idx < 5 * 128; idx += THREADS) {
        int i = idx >> 7, j = idx & 127;
        int band = (g & 1) * 5 + i;
        s_wout[idx] = wout[band * 128 + j];
    }
    if (tid < 5) s_boutv[tid] = bout[(g & 1) * 5 + tid];
    if (tid < 128) { s_h0[0][tid] = 0.f; s_h0[1][tid] = 0.f; s_h1[0][tid] = 0.f; s_h1[1][tid] = 0.f; }
    if (tid < 16) s_mslot[tid >> 3][tid & 7] = 0xF;
    if (tid == 0) {
        mbar_init(smem_u32(&s_barH0), 4);    // 1 aggregated arrive per group CTA
        mbar_init(smem_u32(&s_barH1), 12);   // 4 group h1 + 8 masks
    }
    __syncthreads();
    cluster_sync_all();

    const uint32_t barH0_l = smem_u32(&s_barH0);
    const uint32_t barH1_l = smem_u32(&s_barH1);
    const uint32_t bh0_0 = smem_u32(&s_h0[0][0]), bh0_1 = smem_u32(&s_h0[1][0]);
    const uint32_t bh1_0 = smem_u32(&s_h1[0][0]), bh1_1 = smem_u32(&s_h1[1][0]);
    const uint32_t bmsk0 = smem_u32(&s_mslot[0][rank]);
    const uint32_t bmsk1 = smem_u32(&s_mslot[1][rank]);
    float c0r = 0.f, c1r = 0.f;
    float hist[4][4];
    if (tid < 32) {
        #pragma unroll
        for (int p = 0; p < 4; p++)
            #pragma unroll
            for (int i = 0; i < 4; i++) hist[p][i] = 1e30f;
    }

    int td = T_STEPS, per = 1;

    for (int t = 0; t <= T_STEPS; t++) {
        // ===== layer 0 gates (h0(t-1)) — reg weights, f32x2 =====
        {
            const float* h = s_h0[(t + 1) & 1];
            uint64_t aL = 0ull, aH = 0ull;
            const ulonglong2* h2 = (const ulonglong2*)(h + (khalf << 6));
            #pragma unroll
            for (int i = 0; i < 16; i++) {
                ulonglong2 hv = h2[i];
                fma2(aL, w0r[i].x, hv.x);
                fma2(aH, w0r[i].y, hv.y);
            }
            float2 lo = unpk(aL), hi = unpk(aH);
            float a0 = lo.x + lo.y + hi.x + hi.y;
            if (khalf == 0) a0 += s_xp0[r];
            s_g0p[khalf][r] = a0;
        }

        // ===== wait h1(t-1)+masks; break check (uniform across all 8 CTAs) =====
        if (t > 0) {
            mbar_wait_parity(barH1_l, (uint32_t)((t - 1) & 1));
            int sl = (t - 1) & 1;
            int mdet = s_mslot[sl][0] & s_mslot[sl][1] & s_mslot[sl][2] & s_mslot[sl][3]
                     & s_mslot[sl][4] & s_mslot[sl][5] & s_mslot[sl][6] & s_mslot[sl][7];
            bool brk = (t == T_STEPS) || (t > 10 && mdet != 0);
            if (brk) {
                if (g < 2 && wi >= 2 && wi < 7) {   // final head for step t-1
                    int i = wi - 2;
                    int band = g * 5 + i;
                    float4 hv = *(const float4*)(&s_h1[sl][lane * 4]);
                    float4 wv = *(const float4*)(&s_wout[i * 128 + lane * 4]);
                    float a = hv.x * wv.x + hv.y * wv.y + hv.z * wv.z + hv.w * wv.w;
                    a += __shfl_xor_sync(0xffffffffu, a, 16);
                    a += __shfl_xor_sync(0xffffffffu, a, 8);
                    a += __shfl_xor_sync(0xffffffffu, a, 4);
                    a += __shfl_xor_sync(0xffffffffu, a, 2);
                    a += __shfl_xor_sync(0xffffffffu, a, 1);
                    if (lane == 0)
                        out[(size_t)b_idx * T_STEPS * NB + (size_t)(t - 1) * NB + band] = a + s_boutv[i];
                }
                if (t < T_STEPS) {
                    per = (mdet & 1) ? 1 : ((mdet & 2) ? 2 : ((mdet & 4) ? 3 : 4));
                    td = t;
                }
                break;
            }
        }
        __syncthreads();   // s_g0p ready for cell0

        // ===== cell0 (warp 0)  ||  head(t-1) (warps 2-6 of g<2 CTAs) =====
        float h0v = 0.f;
        if (tid < 32) {
            float gi = s_g0p[0][tid]      + s_g0p[1][tid];
            float gf = s_g0p[0][tid + 32] + s_g0p[1][tid + 32];
            float gg = s_g0p[0][tid + 64] + s_g0p[1][tid + 64];
            float go = s_g0p[0][tid + 96] + s_g0p[1][tid + 96];
            c0r = sigm(gf) * c0r + sigm(gi) * tanhx(gg);
            h0v = sigm(go) * tanhx(c0r);
            int sl = t & 1;
            uint32_t lh0 = (sl ? bh0_1 : bh0_0) + (uint32_t)(((g << 5) + tid) << 2);
            #pragma unroll
            for (int rr = 0; rr < 4; rr++)
                st_cluster_f32(mapa_rank(lh0, (uint32_t)(grpbase + rr)), h0v);
            __syncwarp();
            if (lane < 4) mbar_arrive_cluster(mapa_rank(barH0_l, (uint32_t)(grpbase + lane)));
        } else if (t > 0 && g < 2 && wi >= 2 && wi < 7) {
            int sl = (t - 1) & 1;
            int i = wi - 2;
            int band = g * 5 + i;
            float4 hv = *(const float4*)(&s_h1[sl][lane * 4]);
            float4 wv = *(const float4*)(&s_wout[i * 128 + lane * 4]);
            float a = hv.x * wv.x + hv.y * wv.y + hv.z * wv.z + hv.w * wv.w;
            a += __shfl_xor_sync(0xffffffffu, a, 16);
            a += __shfl_xor_sync(0xffffffffu, a, 8);
            a += __shfl_xor_sync(0xffffffffu, a, 4);
            a += __shfl_xor_sync(0xffffffffu, a, 2);
            a += __shfl_xor_sync(0xffffffffu, a, 1);
            if (lane == 0)
                out[(size_t)b_idx * T_STEPS * NB + (size_t)(t - 1) * NB + band] = a + s_boutv[i];
        }

        // ===== layer 1 gates: whh1 first (hides h0 exchange), then wait, then wih1 =====
        {
            uint64_t aL = 0ull, aH = 0ull;
            {
                const float* h = s_h1[(t + 1) & 1];     // h1(t-1)
                const ulonglong2* h2 = (const ulonglong2*)(h + (khalf << 6));
                #pragma unroll
                for (int i = 0; i < 16; i++) {
                    ulonglong2 hv = h2[i];
                    fma2(aL, w1r[i].x, hv.x);
                    fma2(aH, w1r[i].y, hv.y);
                }
            }
            mbar_wait_parity(barH0_l, (uint32_t)(t & 1));
            {
                const float* h = s_h0[t & 1];           // h0(t)
                const ulonglong2* h2 = (const ulonglong2*)(h + (khalf << 6));
                #pragma unroll
                for (int i = 0; i < 16; i++) {
                    ulonglong2 hv = h2[i];
                    fma2(aL, wi1r[i].x, hv.x);
                    fma2(aH, wi1r[i].y, hv.y);
                }
            }
            float2 lo = unpk(aL), hi = unpk(aH);
            float a0 = lo.x + lo.y + hi.x + hi.y;
            if (khalf == 0) a0 += s_b1[r];
            s_g1p[khalf][r] = a0;
        }
        __syncthreads();

        // ===== cell1 + h1 exchange + epsilon detection + mask publish =====
        if (tid < 32) {
            float gi = s_g1p[0][tid]      + s_g1p[1][tid];
            float gf = s_g1p[0][tid + 32] + s_g1p[1][tid + 32];
            float gg = s_g1p[0][tid + 64] + s_g1p[1][tid + 64];
            float go = s_g1p[0][tid + 96] + s_g1p[1][tid + 96];
            c1r = sigm(gf) * c1r + sigm(gi) * tanhx(gg);
            float h1v = sigm(go) * tanhx(c1r);
            int sl = t & 1;
            uint32_t lh1 = (sl ? bh1_1 : bh1_0) + (uint32_t)(((g << 5) + tid) << 2);
            #pragma unroll
            for (int rr = 0; rr < 4; rr++)
                st_cluster_f32(mapa_rank(lh1, (uint32_t)(grpbase + rr)), h1v);
            int m = 0;
            #pragma unroll
            for (int p = 1; p <= 4; p++) {
                int hs = (t - p) & 3;
                int e = (fabsf(h0v - hist[hs][0]) <= EPS_DET) &&
                        (fabsf(c0r - hist[hs][1]) <= EPS_DET) &&
                        (fabsf(h1v - hist[hs][2]) <= EPS_DET) &&
                        (fabsf(c1r - hist[hs][3]) <= EPS_DET);
                m |= e << (p - 1);
            }
            int ts = t & 3;
            hist[ts][0] = h0v; hist[ts][1] = c0r; hist[ts][2] = h1v; hist[ts][3] = c1r;
            m = __reduce_and_sync(0xFFFFFFFFu, m);
            __syncwarp();                               // h1 stores complete warp-wide
            if (lane < 4) mbar_arrive_cluster(mapa_rank(barH1_l, (uint32_t)(grpbase + lane)));
            if (lane < 8) {
                st_cluster_u32(mapa_rank(sl ? bmsk1 : bmsk0, (uint32_t)lane), (uint32_t)m);
                mbar_arrive_cluster(mapa_rank(barH1_l, (uint32_t)lane));
            }
        }
    }

    cluster_sync_all();
    if (rank == 0 && tid == 0) { g_fix[0] = td; g_fix[1] = per; }
}

// ---------------- parallel periodic tail fill: 2 output rows per thread ----------------
__global__ void k_fill(float* __restrict__ out) {
    __shared__ float s_pat[2][4][10];
    int td = g_fix[0], p = g_fix[1];
    int tt = threadIdx.x;
    if (tt < 80) {
        int b = tt / 40, rr = tt % 40, pp = rr / 10, k = rr % 10;
        int src = td - p + (pp % p);
        s_pat[b][pp][k] = (src >= 0) ? out[((size_t)b * T_STEPS + src) * NB + k] : 0.f;
    }
    __syncthreads();
    int idx = blockIdx.x * blockDim.x + threadIdx.x;
    if (idx >= NOUT / 20) return;
    size_t f0 = (size_t)idx * 20;
    int b  = (f0 >= (size_t)T10) ? 1 : 0;
    int fb = (int)(f0 - (size_t)b * T10);
    int t0 = fb / 10;                      // even; thread covers rows t0, t0+1
    if (t0 + 1 < td) return;
    int q1 = t0 + 1 - td;
    int pp1 = q1 - (q1 / p) * p;
    if (t0 >= td) {
        int q0 = t0 - td;
        int pp0 = q0 - (q0 / p) * p;
        float v[20];
        #pragma unroll
        for (int k = 0; k < 10; k++) { v[k] = s_pat[b][pp0][k]; v[10 + k] = s_pat[b][pp1][k]; }
        float4* o4 = (float4*)(out + f0);
        #pragma unroll
        for (int j = 0; j < 5; j++) {
            float4 w; w.x = v[4*j]; w.y = v[4*j+1]; w.z = v[4*j+2]; w.w = v[4*j+3];
            o4[j] = w;
        }
    } else {   // t0 == td-1: only the second row belongs to the tail
        #pragma unroll
        for (int k = 0; k < 10; k++) out[f0 + 10 + k] = s_pat[b][pp1][k];
    }
}

// ---------------- launch ----------------
extern "C" void kernel_launch(void* const* d_in, const int* in_sizes, int n_in,
                              void* d_out, int out_size) {
    const float* x     = (const float*)d_in[0];
    const float* w1    = (const float*)d_in[1];
    const float* b1    = (const float*)d_in[2];
    const float* w2    = (const float*)d_in[3];
    const float* b2    = (const float*)d_in[4];
    const float* w_ih0 = (const float*)d_in[5];
    const float* w_hh0 = (const float*)d_in[6];
    const float* b_ih0 = (const float*)d_in[7];
    const float* b_hh0 = (const float*)d_in[8];
    const float* w_ih1 = (const float*)d_in[9];
    const float* w_hh1 = (const float*)d_in[10];
    const float* b_ih1 = (const float*)d_in[11];
    const float* b_hh1 = (const float*)d_in[12];
    const float* w_out = (const float*)d_in[13];
    const float* b_out = (const float*)d_in[14];
    float* out = (float*)d_out;

    k_seq<<<CLUSTER_N, THREADS>>>(x, w1, b1, w2, b2, w_ih0,
                                  b_ih0, b_hh0, w_hh0,
                                  w_ih1, w_hh1, b_ih1, b_hh1, w_out, b_out, out);
    k_fill<<<(NOUT / 20 + 255) / 256, 256>>>(out);
}

// round 9
// speedup vs baseline: 21832.7082x; 1.0005x over previous
#include <cuda_runtime.h>
#include <math.h>
#include <stdint.h>

#define T_STEPS 144000
#define NB 10
#define NOUT (2*T_STEPS*NB)
#define T10 (T_STEPS*NB)
#define EPS_DET 1e-4f
#define CLUSTER_N 8
#define THREADS 256

__device__ int g_fix[2];   // {t_detect, period}

// ---------------- PTX helpers ----------------
__device__ __forceinline__ uint32_t smem_u32(const void* p) {
    uint32_t a;
    asm("{ .reg .u64 t; cvta.to.shared.u64 t, %1; cvt.u32.u64 %0, t; }" : "=r"(a) : "l"(p));
    return a;
}
__device__ __forceinline__ uint32_t mapa_rank(uint32_t local, uint32_t rank) {
    uint32_t r;
    asm("mapa.shared::cluster.u32 %0, %1, %2;" : "=r"(r) : "r"(local), "r"(rank));
    return r;
}
__device__ __forceinline__ void st_cluster_f32(uint32_t addr, float v) {
    asm volatile("st.shared::cluster.f32 [%0], %1;" :: "r"(addr), "f"(v) : "memory");
}
__device__ __forceinline__ void st_cluster_u32(uint32_t addr, uint32_t v) {
    asm volatile("st.shared::cluster.u32 [%0], %1;" :: "r"(addr), "r"(v) : "memory");
}
__device__ __forceinline__ void mbar_init(uint32_t addr, uint32_t cnt) {
    asm volatile("mbarrier.init.shared.b64 [%0], %1;" :: "r"(addr), "r"(cnt) : "memory");
}
__device__ __forceinline__ void mbar_arrive_cluster(uint32_t addr) {
    asm volatile("mbarrier.arrive.release.cluster.shared::cluster.b64 _, [%0];"
                 :: "r"(addr) : "memory");
}
__device__ __forceinline__ void mbar_wait_parity(uint32_t addr, uint32_t parity) {
    asm volatile(
        "{\n\t.reg .pred P;\n\t"
        "WLP_%=:\n\t"
        "mbarrier.try_wait.parity.acquire.cluster.shared::cta.b64 P, [%0], %1, 0x989680;\n\t"
        "@P bra.uni WDN_%=;\n\t"
        "bra.uni WLP_%=;\n\t"
        "WDN_%=:\n\t}"
        :: "r"(addr), "r"(parity) : "memory");
}
__device__ __forceinline__ void cluster_sync_all() {
    asm volatile("barrier.cluster.arrive.aligned;" ::: "memory");
    asm volatile("barrier.cluster.wait.aligned;" ::: "memory");
}
__device__ __forceinline__ uint32_t ctarank() {
    uint32_t r; asm("mov.u32 %0, %%cluster_ctarank;" : "=r"(r)); return r;
}
// packed f32x2 fma
__device__ __forceinline__ void fma2(uint64_t& d, uint64_t a, uint64_t b) {
    asm("fma.rn.f32x2 %0, %1, %2, %0;" : "+l"(d) : "l"(a), "l"(b));
}
__device__ __forceinline__ float2 unpk(uint64_t v) {
    float2 r; asm("mov.b64 {%0, %1}, %2;" : "=f"(r.x), "=f"(r.y) : "l"(v)); return r;
}
// fast gates: MUFU-based, rel err ~1e-6
__device__ __forceinline__ float ex2a(float x) { float r; asm("ex2.approx.f32 %0, %1;" : "=f"(r) : "f"(x)); return r; }
__device__ __forceinline__ float rcpa(float x) { float r; asm("rcp.approx.f32 %0, %1;" : "=f"(r) : "f"(x)); return r; }
__device__ __forceinline__ float sigm(float v)  { return rcpa(1.0f + ex2a(-1.4426950408889634f * v)); }
__device__ __forceinline__ float tanhx(float v) { return 1.0f - 2.0f * rcpa(1.0f + ex2a(2.8853900817779268f * v)); }

// ---------------- clustered sequential kernel (batch-split, reg-resident weights) ----------------
__global__ void __launch_bounds__(THREADS, 1) __cluster_dims__(CLUSTER_N, 1, 1)
k_seq(const float* __restrict__ x,
      const float* __restrict__ w1e,  const float* __restrict__ eb1,
      const float* __restrict__ w2e,  const float* __restrict__ eb2,
      const float* __restrict__ wih0,
      const float* __restrict__ bih0, const float* __restrict__ bhh0,
      const float* __restrict__ whh0,
      const float* __restrict__ wih1, const float* __restrict__ whh1,
      const float* __restrict__ bih1, const float* __restrict__ bhh1,
      const float* __restrict__ wout, const float* __restrict__ bout,
      float* __restrict__ out) {
    __shared__ __align__(16) float s_h0[2][128];   // [slot][unit]
    __shared__ __align__(16) float s_h1[2][128];
    __shared__ float s_g0p[2][128];                // [khalf][r]
    __shared__ float s_g1p[2][128];
    __shared__ float s_xp0[128];
    __shared__ float s_b1[128];
    __shared__ __align__(16) float s_wout[5*128];
    __shared__ float s_boutv[8];
    __shared__ float s_l1[128];
    __shared__ __align__(16) float s_l2[256];
    __shared__ int   s_mslot[2][8];                // [slot][src rank]
    __shared__ __align__(8) unsigned long long s_barH0, s_barH1;

    const int tid = threadIdx.x;
    const uint32_t rank = ctarank();
    const int g = (int)(rank & 3);                 // quarter within batch group
    const int grpbase = (int)(rank & 4);           // 0 or 4
    const int b_idx = (int)(rank >> 2);            // batch this CTA runs
    const int r = tid & 127;
    const int khalf = tid >> 7;
    const int wi = tid >> 5;
    const int lane = tid & 31;
    const int grow = ((r >> 5) << 7) + (g << 5) + (r & 31);  // global gate row

    // ---- register-resident weights: this thread's gate rows, its k-half ----
    ulonglong2 w0r[16], w1r[16], wi1r[16];
    {
        const ulonglong2* s0 = (const ulonglong2*)(whh0 + grow * 128 + (khalf << 6));
        const ulonglong2* s1 = (const ulonglong2*)(whh1 + grow * 128 + (khalf << 6));
        const ulonglong2* s2 = (const ulonglong2*)(wih1 + grow * 128 + (khalf << 6));
        #pragma unroll
        for (int i = 0; i < 16; i++) { w0r[i] = s0[i]; w1r[i] = s1[i]; wi1r[i] = s2[i]; }
    }

    // ---- encoder MLP (redundant per CTA) ----
    if (tid < 128) { int b = tid >> 6, j = tid & 63;
        float a = eb1[j];
        #pragma unroll
        for (int k = 0; k < 16; k++) a += x[b * 16 + k] * w1e[j * 16 + k];
        s_l1[b * 64 + j] = fmaxf(a, 0.f);
    }
    __syncthreads();
    { int b = tid >> 7, j = tid & 127;
        float a = eb2[j];
        #pragma unroll 8
        for (int k = 0; k < 64; k++) a += s_l1[b * 64 + k] * w2e[j * 64 + k];
        s_l2[b * 128 + j] = fmaxf(a, 0.f);
    }
    __syncthreads();
    if (tid < 128) {   // xp0 for THIS batch only
        float a = bih0[grow] + bhh0[grow];
        const float4* l2v = (const float4*)(s_l2 + b_idx * 128);
        const float4* w0v = (const float4*)wih0;
        #pragma unroll 8
        for (int k4 = 0; k4 < 32; k4++) {
            float4 w = w0v[grow * 32 + k4];
            float4 l = l2v[k4];
            a += w.x * l.x + w.y * l.y + w.z * l.z + w.w * l.w;
        }
        s_xp0[r] = a;
        s_b1[r] = bih1[grow] + bhh1[grow];
    }
    for (int idx = tid; idx < 5 * 128; idx += THREADS) {
        int i = idx >> 7, j = idx & 127;
        int band = (g & 1) * 5 + i;
        s_wout[idx] = wout[band * 128 + j];
    }
    if (tid < 5) s_boutv[tid] = bout[(g & 1) * 5 + tid];
    if (tid < 128) { s_h0[0][tid] = 0.f; s_h0[1][tid] = 0.f; s_h1[0][tid] = 0.f; s_h1[1][tid] = 0.f; }
    if (tid < 16) s_mslot[tid >> 3][tid & 7] = 0xF;
    if (tid == 0) {
        mbar_init(smem_u32(&s_barH0), 4);    // 1 aggregated arrive per group CTA
        mbar_init(smem_u32(&s_barH1), 12);   // 4 group h1 + 8 masks
    }
    __syncthreads();
    cluster_sync_all();

    const uint32_t barH0_l = smem_u32(&s_barH0);
    const uint32_t barH1_l = smem_u32(&s_barH1);
    const uint32_t bh0_0 = smem_u32(&s_h0[0][0]), bh0_1 = smem_u32(&s_h0[1][0]);
    const uint32_t bh1_0 = smem_u32(&s_h1[0][0]), bh1_1 = smem_u32(&s_h1[1][0]);
    const uint32_t bmsk0 = smem_u32(&s_mslot[0][rank]);
    const uint32_t bmsk1 = smem_u32(&s_mslot[1][rank]);
    float c0r = 0.f, c1r = 0.f;
    float hist[4][4];
    if (tid < 32) {
        #pragma unroll
        for (int p = 0; p < 4; p++)
            #pragma unroll
            for (int i = 0; i < 4; i++) hist[p][i] = 1e30f;
    }

    int td = T_STEPS, per = 1;

    for (int t = 0; t <= T_STEPS; t++) {
        // ===== layer 0 gates (h0(t-1)) — reg weights, f32x2 =====
        {
            const float* h = s_h0[(t + 1) & 1];
            uint64_t aL = 0ull, aH = 0ull;
            const ulonglong2* h2 = (const ulonglong2*)(h + (khalf << 6));
            #pragma unroll
            for (int i = 0; i < 16; i++) {
                ulonglong2 hv = h2[i];
                fma2(aL, w0r[i].x, hv.x);
                fma2(aH, w0r[i].y, hv.y);
            }
            float2 lo = unpk(aL), hi = unpk(aH);
            float a0 = lo.x + lo.y + hi.x + hi.y;
            if (khalf == 0) a0 += s_xp0[r];
            s_g0p[khalf][r] = a0;
        }

        // ===== wait h1(t-1)+masks; break check (uniform across all 8 CTAs) =====
        if (t > 0) {
            mbar_wait_parity(barH1_l, (uint32_t)((t - 1) & 1));
            int sl = (t - 1) & 1;
            int mdet = s_mslot[sl][0] & s_mslot[sl][1] & s_mslot[sl][2] & s_mslot[sl][3]
                     & s_mslot[sl][4] & s_mslot[sl][5] & s_mslot[sl][6] & s_mslot[sl][7];
            bool brk = (t == T_STEPS) || (t > 10 && mdet != 0);
            if (brk) {
                if (g < 2 && wi >= 2 && wi < 7) {   // final head for step t-1
                    int i = wi - 2;
                    int band = g * 5 + i;
                    float4 hv = *(const float4*)(&s_h1[sl][lane * 4]);
                    float4 wv = *(const float4*)(&s_wout[i * 128 + lane * 4]);
                    float a = hv.x * wv.x + hv.y * wv.y + hv.z * wv.z + hv.w * wv.w;
                    a += __shfl_xor_sync(0xffffffffu, a, 16);
                    a += __shfl_xor_sync(0xffffffffu, a, 8);
                    a += __shfl_xor_sync(0xffffffffu, a, 4);
                    a += __shfl_xor_sync(0xffffffffu, a, 2);
                    a += __shfl_xor_sync(0xffffffffu, a, 1);
                    if (lane == 0)
                        out[(size_t)b_idx * T_STEPS * NB + (size_t)(t - 1) * NB + band] = a + s_boutv[i];
                }
                if (t < T_STEPS) {
                    per = (mdet & 1) ? 1 : ((mdet & 2) ? 2 : ((mdet & 4) ? 3 : 4));
                    td = t;
                }
                break;
            }
        }
        __syncthreads();   // s_g0p ready for cell0

        // ===== cell0 (warp 0)  ||  head(t-1) (warps 2-6 of g<2 CTAs) =====
        float h0v = 0.f;
        if (tid < 32) {
            float gi = s_g0p[0][tid]      + s_g0p[1][tid];
            float gf = s_g0p[0][tid + 32] + s_g0p[1][tid + 32];
            float gg = s_g0p[0][tid + 64] + s_g0p[1][tid + 64];
            float go = s_g0p[0][tid + 96] + s_g0p[1][tid + 96];
            c0r = sigm(gf) * c0r + sigm(gi) * tanhx(gg);
            h0v = sigm(go) * tanhx(c0r);
            int sl = t & 1;
            uint32_t lh0 = (sl ? bh0_1 : bh0_0) + (uint32_t)(((g << 5) + tid) << 2);
            #pragma unroll
            for (int rr = 0; rr < 4; rr++)
                st_cluster_f32(mapa_rank(lh0, (uint32_t)(grpbase + rr)), h0v);
            __syncwarp();
            if (lane < 4) mbar_arrive_cluster(mapa_rank(barH0_l, (uint32_t)(grpbase + lane)));
        } else if (t > 0 && g < 2 && wi >= 2 && wi < 7) {
            int sl = (t - 1) & 1;
            int i = wi - 2;
            int band = g * 5 + i;
            float4 hv = *(const float4*)(&s_h1[sl][lane * 4]);
            float4 wv = *(const float4*)(&s_wout[i * 128 + lane * 4]);
            float a = hv.x * wv.x + hv.y * wv.y + hv.z * wv.z + hv.w * wv.w;
            a += __shfl_xor_sync(0xffffffffu, a, 16);
            a += __shfl_xor_sync(0xffffffffu, a, 8);
            a += __shfl_xor_sync(0xffffffffu, a, 4);
            a += __shfl_xor_sync(0xffffffffu, a, 2);
            a += __shfl_xor_sync(0xffffffffu, a, 1);
            if (lane == 0)
                out[(size_t)b_idx * T_STEPS * NB + (size_t)(t - 1) * NB + band] = a + s_boutv[i];
        }

        // ===== layer 1 gates: whh1 first (hides h0 exchange), then wait, then wih1 =====
        {
            uint64_t aL = 0ull, aH = 0ull;
            {
                const float* h = s_h1[(t + 1) & 1];     // h1(t-1)
                const ulonglong2* h2 = (const ulonglong2*)(h + (khalf << 6));
                #pragma unroll
                for (int i = 0; i < 16; i++) {
                    ulonglong2 hv = h2[i];
                    fma2(aL, w1r[i].x, hv.x);
                    fma2(aH, w1r[i].y, hv.y);
                }
            }
            mbar_wait_parity(barH0_l, (uint32_t)(t & 1));
            {
                const float* h = s_h0[t & 1];           // h0(t)
                const ulonglong2* h2 = (const ulonglong2*)(h + (khalf << 6));
                #pragma unroll
                for (int i = 0; i < 16; i++) {
                    ulonglong2 hv = h2[i];
                    fma2(aL, wi1r[i].x, hv.x);
                    fma2(aH, wi1r[i].y, hv.y);
                }
            }
            float2 lo = unpk(aL), hi = unpk(aH);
            float a0 = lo.x + lo.y + hi.x + hi.y;
            if (khalf == 0) a0 += s_b1[r];
            s_g1p[khalf][r] = a0;
        }
        __syncthreads();

        // ===== cell1 + h1 exchange + epsilon detection + mask publish =====
        if (tid < 32) {
            float gi = s_g1p[0][tid]      + s_g1p[1][tid];
            float gf = s_g1p[0][tid + 32] + s_g1p[1][tid + 32];
            float gg = s_g1p[0][tid + 64] + s_g1p[1][tid + 64];
            float go = s_g1p[0][tid + 96] + s_g1p[1][tid + 96];
            c1r = sigm(gf) * c1r + sigm(gi) * tanhx(gg);
            float h1v = sigm(go) * tanhx(c1r);
            int sl = t & 1;
            uint32_t lh1 = (sl ? bh1_1 : bh1_0) + (uint32_t)(((g << 5) + tid) << 2);
            #pragma unroll
            for (int rr = 0; rr < 4; rr++)
                st_cluster_f32(mapa_rank(lh1, (uint32_t)(grpbase + rr)), h1v);
            int m = 0;
            #pragma unroll
            for (int p = 1; p <= 4; p++) {
                int hs = (t - p) & 3;
                int e = (fabsf(h0v - hist[hs][0]) <= EPS_DET) &&
                        (fabsf(c0r - hist[hs][1]) <= EPS_DET) &&
                        (fabsf(h1v - hist[hs][2]) <= EPS_DET) &&
                        (fabsf(c1r - hist[hs][3]) <= EPS_DET);
                m |= e << (p - 1);
            }
            int ts = t & 3;
            hist[ts][0] = h0v; hist[ts][1] = c0r; hist[ts][2] = h1v; hist[ts][3] = c1r;
            m = __reduce_and_sync(0xFFFFFFFFu, m);
            __syncwarp();                               // h1 stores complete warp-wide
            if (lane < 4) mbar_arrive_cluster(mapa_rank(barH1_l, (uint32_t)(grpbase + lane)));
            if (lane < 8) {
                st_cluster_u32(mapa_rank(sl ? bmsk1 : bmsk0, (uint32_t)lane), (uint32_t)m);
                mbar_arrive_cluster(mapa_rank(barH1_l, (uint32_t)lane));
            }
        }
    }

    cluster_sync_all();
    if (rank == 0 && tid == 0) { g_fix[0] = td; g_fix[1] = per; }
}

// ---------------- parallel periodic tail fill: 2 output rows per thread ----------------
__global__ void k_fill(float* __restrict__ out) {
    __shared__ float s_pat[2][4][10];
    int td = g_fix[0], p = g_fix[1];
    int tt = threadIdx.x;
    if (tt < 80) {
        int b = tt / 40, rr = tt % 40, pp = rr / 10, k = rr % 10;
        int src = td - p + (pp % p);
        s_pat[b][pp][k] = (src >= 0) ? out[((size_t)b * T_STEPS + src) * NB + k] : 0.f;
    }
    __syncthreads();
    int idx = blockIdx.x * blockDim.x + threadIdx.x;
    if (idx >= NOUT / 20) return;
    size_t f0 = (size_t)idx * 20;
    int b  = (f0 >= (size_t)T10) ? 1 : 0;
    int fb = (int)(f0 - (size_t)b * T10);
    int t0 = fb / 10;                      // even; thread covers rows t0, t0+1
    if (t0 + 1 < td) return;
    int q1 = t0 + 1 - td;
    int pp1 = q1 - (q1 / p) * p;
    if (t0 >= td) {
        int q0 = t0 - td;
        int pp0 = q0 - (q0 / p) * p;
        float v[20];
        #pragma unroll
        for (int k = 0; k < 10; k++) { v[k] = s_pat[b][pp0][k]; v[10 + k] = s_pat[b][pp1][k]; }
        float4* o4 = (float4*)(out + f0);
        #pragma unroll
        for (int j = 0; j < 5; j++) {
            float4 w; w.x = v[4*j]; w.y = v[4*j+1]; w.z = v[4*j+2]; w.w = v[4*j+3];
            o4[j] = w;
        }
    } else {   // t0 == td-1: only the second row belongs to the tail
        #pragma unroll
        for (int k = 0; k < 10; k++) out[f0 + 10 + k] = s_pat[b][pp1][k];
    }
}

// ---------------- launch ----------------
extern "C" void kernel_launch(void* const* d_in, const int* in_sizes, int n_in,
                              void* d_out, int out_size) {
    const float* x     = (const float*)d_in[0];
    const float* w1    = (const float*)d_in[1];
    const float* b1    = (const float*)d_in[2];
    const float* w2    = (const float*)d_in[3];
    const float* b2    = (const float*)d_in[4];
    const float* w_ih0 = (const float*)d_in[5];
    const float* w_hh0 = (const float*)d_in[6];
    const float* b_ih0 = (const float*)d_in[7];
    const float* b_hh0 = (const float*)d_in[8];
    const float* w_ih1 = (const float*)d_in[9];
    const float* w_hh1 = (const float*)d_in[10];
    const float* b_ih1 = (const float*)d_in[11];
    const float* b_hh1 = (const float*)d_in[12];
    const float* w_out = (const float*)d_in[13];
    const float* b_out = (const float*)d_in[14];
    float* out = (float*)d_out;

    k_seq<<<CLUSTER_N, THREADS>>>(x, w1, b1, w2, b2, w_ih0,
                                  b_ih0, b_hh0, w_hh0,
                                  w_ih1, w_hh1, b_ih1, b_hh1, w_out, b_out, out);
    k_fill<<<(NOUT / 20 + 255) / 256, 256>>>(out);
}